// round 1
// baseline (speedup 1.0000x reference)
#include <cuda_runtime.h>

// Problem constants
#define BB    8
#define NN    4096
#define DIMV  768
#define HEADS 12
#define HD    64
#define EDIM  1536
#define MTOT  (BB*NN)   // 32768

// Scratch (static device allocations — allowed; ~508 MB total)
__device__ float g_q   [(size_t)MTOT * DIMV];   // x @ w_q                (B,N,768)
__device__ float g_kv  [(size_t)MTOT * EDIM];   // x @ w_kv; k cols 0..767 softmaxed in place
__device__ float g_y   [(size_t)MTOT * EDIM];   // scale*attn, then += lepe
__device__ float g_ktv [BB * HEADS * HD * HD];  // (B,12,64,64)
__device__ float g_ektv[BB * 2*HEADS * HD * HD];// (B,24,64,64)

// ---------------------------------------------------------------------------
// Classic SGEMM: C[M,N] = A[M,K] @ W[K,N] (+bias). BM=BN=128, BK=8, 8x8/thread.
// Requires M%128==0, N%128==0, K%8==0 (true for all three calls).
// ---------------------------------------------------------------------------
__global__ __launch_bounds__(256) void sgemm128(
    const float* __restrict__ A, const float* __restrict__ W,
    float* __restrict__ C, int M, int N, int K, const float* __restrict__ bias)
{
    __shared__ float As[8][128];
    __shared__ float Bs[8][128];

    const int tid = threadIdx.x;
    const int bx = blockIdx.x, by = blockIdx.y;

    const float* Ab = A + (size_t)by * 128 * K;
    const float* Bb = W + bx * 128;

    const int aRow = tid >> 1, aCol = (tid & 1) * 4;
    const int bRow = tid >> 5, bCol = (tid & 31) * 4;
    const int tx = tid & 15, ty = tid >> 4;

    float acc[8][8];
#pragma unroll
    for (int i = 0; i < 8; i++)
#pragma unroll
        for (int j = 0; j < 8; j++) acc[i][j] = 0.f;

    for (int k0 = 0; k0 < K; k0 += 8) {
        float4 a = *(const float4*)(Ab + (size_t)aRow * K + k0 + aCol);
        As[aCol + 0][aRow] = a.x;
        As[aCol + 1][aRow] = a.y;
        As[aCol + 2][aRow] = a.z;
        As[aCol + 3][aRow] = a.w;
        float4 bv = *(const float4*)(Bb + (size_t)(k0 + bRow) * N + bCol);
        *(float4*)&Bs[bRow][bCol] = bv;
        __syncthreads();

#pragma unroll
        for (int k = 0; k < 8; k++) {
            float ar[8], br[8];
            *(float4*)&ar[0] = *(const float4*)&As[k][ty * 8];
            *(float4*)&ar[4] = *(const float4*)&As[k][ty * 8 + 4];
            *(float4*)&br[0] = *(const float4*)&Bs[k][tx * 8];
            *(float4*)&br[4] = *(const float4*)&Bs[k][tx * 8 + 4];
#pragma unroll
            for (int i = 0; i < 8; i++)
#pragma unroll
                for (int j = 0; j < 8; j++)
                    acc[i][j] += ar[i] * br[j];
        }
        __syncthreads();
    }

    float* Cb = C + (size_t)(by * 128) * N + bx * 128;
#pragma unroll
    for (int i = 0; i < 8; i++) {
#pragma unroll
        for (int j4 = 0; j4 < 8; j4 += 4) {
            float4 v;
            v.x = acc[i][j4 + 0]; v.y = acc[i][j4 + 1];
            v.z = acc[i][j4 + 2]; v.w = acc[i][j4 + 3];
            if (bias) {
                const float* bp = bias + bx * 128 + tx * 8 + j4;
                v.x += bp[0]; v.y += bp[1]; v.z += bp[2]; v.w += bp[3];
            }
            *(float4*)(Cb + (size_t)(ty * 8 + i) * N + tx * 8 + j4) = v;
        }
    }
}

// ---------------------------------------------------------------------------
// Softmax over head_dim (64) for k (cols 0..767 of g_kv), in place.
// One warp per (b,n,h) row; 2 elements per lane.
// ---------------------------------------------------------------------------
__global__ __launch_bounds__(256) void softmax_k_kernel()
{
    int tid = threadIdx.x;
    int warp = tid >> 5, lane = tid & 31;
    long r = (long)blockIdx.x * 8 + warp;         // 0 .. 393215
    int bn = (int)(r / HEADS), h = (int)(r % HEADS);
    float* p = g_kv + (size_t)bn * EDIM + h * HD;

    float v0 = p[lane], v1 = p[lane + 32];
    float m = fmaxf(v0, v1);
#pragma unroll
    for (int o = 16; o > 0; o >>= 1) m = fmaxf(m, __shfl_xor_sync(0xffffffffu, m, o));
    float e0 = expf(v0 - m), e1 = expf(v1 - m);
    float s = e0 + e1;
#pragma unroll
    for (int o = 16; o > 0; o >>= 1) s += __shfl_xor_sync(0xffffffffu, s, o);
    float inv = 1.f / s;
    p[lane] = e0 * inv;
    p[lane + 32] = e1 * inv;
}

// ---------------------------------------------------------------------------
// ktv[b,h,d,e] = sum_n ks[b,h,n,d] * v[b,h,n,e].  One block per (b,h).
// ---------------------------------------------------------------------------
__global__ __launch_bounds__(256) void ktv_kernel()
{
    int bh = blockIdx.x;            // 0..95
    int b = bh / HEADS, h = bh % HEADS;
    const float* ksp = g_kv + (size_t)b * NN * EDIM + h * HD;
    const float* vp  = ksp + DIMV;  // v columns start at 768

    __shared__ float Ks[32][64];
    __shared__ float Vs[32][64];

    int tid = threadIdx.x;
    int td = tid & 15, te = tid >> 4;
    float acc[4][4];
#pragma unroll
    for (int i = 0; i < 4; i++)
#pragma unroll
        for (int j = 0; j < 4; j++) acc[i][j] = 0.f;

    for (int n0 = 0; n0 < NN; n0 += 32) {
#pragma unroll
        for (int i = 0; i < 2; i++) {
            int idx4 = tid + i * 256;             // 0..511
            int nl = idx4 >> 4, d4 = (idx4 & 15) * 4;
            *(float4*)&Ks[nl][d4] = *(const float4*)(ksp + (size_t)(n0 + nl) * EDIM + d4);
            *(float4*)&Vs[nl][d4] = *(const float4*)(vp  + (size_t)(n0 + nl) * EDIM + d4);
        }
        __syncthreads();
#pragma unroll 8
        for (int n = 0; n < 32; n++) {
            float a0[4], b0[4];
            *(float4*)a0 = *(const float4*)&Ks[n][td * 4];
            *(float4*)b0 = *(const float4*)&Vs[n][te * 4];
#pragma unroll
            for (int i = 0; i < 4; i++)
#pragma unroll
                for (int j = 0; j < 4; j++)
                    acc[i][j] += a0[i] * b0[j];
        }
        __syncthreads();
    }

    float* out = g_ktv + (size_t)bh * HD * HD;
#pragma unroll
    for (int i = 0; i < 4; i++) {
        float4 v;
        v.x = acc[i][0]; v.y = acc[i][1]; v.z = acc[i][2]; v.w = acc[i][3];
        *(float4*)&out[(td * 4 + i) * HD + te * 4] = v;
    }
}

// ---------------------------------------------------------------------------
// ektv[b,j,d,e] head-expansion (roll by -32 over the (h,e) flat axis).
// ---------------------------------------------------------------------------
__global__ void build_ektv_kernel()
{
    int idx = blockIdx.x * 256 + threadIdx.x;     // < 786432
    int e = idx & 63;
    int d = (idx >> 6) & 63;
    int bj = idx >> 12;
    int j = bj % 24, b = bj / 24;
    float val;
    if (j < 12) {
        val = g_ktv[(((size_t)(b * 12 + j) * 64) + d) * 64 + e];
    } else {
        int c = (j - 12) * 64 + e + 32;
        if (c >= 768) c -= 768;
        int hp = c >> 6, ep = c & 63;
        val = g_ktv[(((size_t)(b * 12 + hp) * 64) + d) * 64 + ep];
    }
    g_ektv[idx] = val;
}

// ---------------------------------------------------------------------------
// attn: y[b, n, j*64+e] = scale * sum_d eq[b,j,n,d] * ektv[b,j,d,e]
// eq is read directly from g_q via the roll column map (never materialized).
// Block = (b, j, 64-row tile of n).
// ---------------------------------------------------------------------------
__global__ __launch_bounds__(256) void attn_kernel()
{
    int b = blockIdx.z, j = blockIdx.y, n0 = blockIdx.x * 64;
    __shared__ float Es[64][64];
    __shared__ float Qs[64][64];
    int tid = threadIdx.x;

    const float* ep = g_ektv + (size_t)((b * 24 + j) * 64) * 64;
#pragma unroll
    for (int i = 0; i < 4; i++) {
        int idx4 = tid + i * 256;                 // 0..1023
        *(float4*)&Es[idx4 >> 4][(idx4 & 15) * 4] = *(const float4*)(ep + idx4 * 4);
    }

    int qbase = (j < 12) ? j * 64 : ((j - 12) * 64 + 32);
    const float* qp = g_q + (size_t)(b * NN + n0) * DIMV;
#pragma unroll
    for (int i = 0; i < 4; i++) {
        int idx4 = tid + i * 256;
        int nl = idx4 >> 4, d4 = (idx4 & 15) * 4;
        int c = qbase + d4;
        if (c >= 768) c -= 768;
        *(float4*)&Qs[nl][d4] = *(const float4*)(qp + (size_t)nl * DIMV + c);
    }
    __syncthreads();

    int r0 = (tid >> 4) * 4, e0 = (tid & 15) * 4;
    float acc[4][4];
#pragma unroll
    for (int i = 0; i < 4; i++)
#pragma unroll
        for (int jj = 0; jj < 4; jj++) acc[i][jj] = 0.f;

#pragma unroll 8
    for (int d = 0; d < 64; d++) {
        float a0[4], b0[4];
        a0[0] = Qs[r0 + 0][d]; a0[1] = Qs[r0 + 1][d];
        a0[2] = Qs[r0 + 2][d]; a0[3] = Qs[r0 + 3][d];
        *(float4*)b0 = *(const float4*)&Es[d][e0];
#pragma unroll
        for (int i = 0; i < 4; i++)
#pragma unroll
            for (int jj = 0; jj < 4; jj++)
                acc[i][jj] += a0[i] * b0[jj];
    }

    const float scale = 0.125f;                   // 64^-0.5
#pragma unroll
    for (int i = 0; i < 4; i++) {
        float4 v;
        v.x = scale * acc[i][0]; v.y = scale * acc[i][1];
        v.z = scale * acc[i][2]; v.w = scale * acc[i][3];
        *(float4*)(g_y + (size_t)(b * NN + n0 + r0 + i) * EDIM + j * 64 + e0) = v;
    }
}

// ---------------------------------------------------------------------------
// LePE depthwise 3x3 conv over expanded-q laid out as (B, 1536, 64, 64),
// accumulated into g_y (+bias). Tiles: 32 channels x 16x16 spatial.
// Channels-innermost smem layout keeps global loads coalesced over channels.
// ---------------------------------------------------------------------------
__global__ __launch_bounds__(256) void lepe_kernel(
    const float* __restrict__ w_lepe, const float* __restrict__ b_lepe)
{
    __shared__ float In[18][18][32];
    __shared__ float Wt[32][9];
    __shared__ float Bsh[32];

    int b = blockIdx.z;
    int chunk = blockIdx.y;                // 0..47  -> channels c0..c0+31
    int tile = blockIdx.x;                 // 0..15  -> 16x16 spatial tile
    int c0 = chunk * 32;
    int j = c0 >> 6, dlo = c0 & 63;
    int base = (j < 12) ? c0 : ((j - 12) * 64 + 32 + dlo);
    if (base >= 768) base -= 768;          // wrap (only j=23, upper half)
    int ty0 = (tile >> 2) * 16, tx0 = (tile & 3) * 16;
    int tid = threadIdx.x;

    for (int idx = tid; idx < 32 * 9; idx += 256)
        Wt[idx / 9][idx % 9] = w_lepe[c0 * 9 + idx];
    if (tid < 32) Bsh[tid] = b_lepe[c0 + tid];

    const float* qb = g_q + (size_t)b * NN * DIMV + base;
    for (int idx = tid; idx < 18 * 18 * 32; idx += 256) {
        int c = idx & 31;
        int sp = idx >> 5;
        int sy = sp / 18, sx = sp - sy * 18;
        int hh = ty0 + sy - 1, ww = tx0 + sx - 1;
        float v = 0.f;
        if (hh >= 0 && hh < 64 && ww >= 0 && ww < 64)
            v = qb[(size_t)(hh * 64 + ww) * DIMV + c];
        In[sy][sx][c] = v;
    }
    __syncthreads();

    int c = tid & 31, sg = tid >> 5;
    float* yb = g_y + (size_t)b * NN * EDIM + c0 + c;
#pragma unroll 4
    for (int s = 0; s < 32; s++) {
        int sp = sg * 32 + s;
        int sy = sp >> 4, sx = sp & 15;
        float sum = Bsh[c];
#pragma unroll
        for (int ky = 0; ky < 3; ky++)
#pragma unroll
            for (int kx = 0; kx < 3; kx++)
                sum += Wt[c][ky * 3 + kx] * In[sy + ky][sx + kx][c];
        int n = (ty0 + sy) * 64 + (tx0 + sx);
        yb[(size_t)n * EDIM] += sum;
    }
}

// ---------------------------------------------------------------------------
extern "C" void kernel_launch(void* const* d_in, const int* in_sizes, int n_in,
                              void* d_out, int out_size)
{
    const float* x      = (const float*)d_in[0];  // (8,4096,768)
    const float* w_q    = (const float*)d_in[1];  // (768,768)
    const float* w_kv   = (const float*)d_in[2];  // (768,1536)
    const float* w_proj = (const float*)d_in[3];  // (1536,768)
    const float* b_proj = (const float*)d_in[4];  // (768)
    const float* w_lepe = (const float*)d_in[5];  // (1536,1,3,3)
    const float* b_lepe = (const float*)d_in[6];  // (1536)
    float* out = (float*)d_out;                   // (8,4096,768)

    float* q = nullptr; float* kv = nullptr; float* y = nullptr;
    cudaGetSymbolAddress((void**)&q,  g_q);
    cudaGetSymbolAddress((void**)&kv, g_kv);
    cudaGetSymbolAddress((void**)&y,  g_y);

    // 1-2: input projections
    sgemm128<<<dim3(DIMV / 128, MTOT / 128), 256>>>(x, w_q,  q,  MTOT, DIMV, DIMV, nullptr);
    sgemm128<<<dim3(EDIM / 128, MTOT / 128), 256>>>(x, w_kv, kv, MTOT, EDIM, DIMV, nullptr);

    // 3: softmax over head_dim on k
    softmax_k_kernel<<<(MTOT * HEADS) / 8, 256>>>();

    // 4: K^T V per (b,h)
    ktv_kernel<<<BB * HEADS, 256>>>();

    // 5: head-expand ktv
    build_ektv_kernel<<<(BB * 24 * HD * HD) / 256, 256>>>();

    // 6: attn = eq @ ektv  (scaled) -> y
    attn_kernel<<<dim3(NN / 64, 24, BB), 256>>>();

    // 7: LePE conv accumulated into y
    lepe_kernel<<<dim3(16, EDIM / 32, BB), 256>>>(w_lepe, b_lepe);

    // 8: output projection + bias
    sgemm128<<<dim3(DIMV / 128, MTOT / 128), 256>>>(y, w_proj, out, MTOT, DIMV, EDIM, b_proj);
}

// round 2
// speedup vs baseline: 1.1731x; 1.1731x over previous
#include <cuda_runtime.h>
#include <cuda_bf16.h>
#include <cstdint>

// Problem constants
#define BB    8
#define NN    4096
#define DIMV  768
#define HEADS 12
#define HD    64
#define EDIM  1536
#define MTOT  (BB*NN)   // 32768
#define KTV_SPLIT 16

// Scratch (static device allocations)
__device__ float g_q   [(size_t)MTOT * DIMV];
__device__ float g_kv  [(size_t)MTOT * EDIM];
__device__ float g_y   [(size_t)MTOT * EDIM];
__device__ float g_ktv [BB * HEADS * HD * HD];
__device__ float g_ktvp[(size_t)KTV_SPLIT * BB * HEADS * HD * HD]; // partials
__device__ float g_ektv[BB * 2*HEADS * HD * HD];

// ---------------------------------------------------------------------------
// bf16x3 tensor-core GEMM: C[M,N] = A[M,K] @ W[K,N] (+bias), fp32 in/out.
// Block 128x128, BK=32, 256 threads (8 warps of 32x64). A,B split into
// bf16 hi+lo on the fly; 3 MMA passes (hh, hl, lh) share fp32 accumulators.
// Requires M%128==0, N%128==0, K%32==0.
// ---------------------------------------------------------------------------
__device__ __forceinline__ void ldsm_x4(uint32_t r[4], const __nv_bfloat16* p) {
    uint32_t a = (uint32_t)__cvta_generic_to_shared(p);
    asm volatile("ldmatrix.sync.aligned.m8n8.x4.shared.b16 {%0,%1,%2,%3}, [%4];"
                 : "=r"(r[0]), "=r"(r[1]), "=r"(r[2]), "=r"(r[3]) : "r"(a));
}

__device__ __forceinline__ void mma16816(float c[4], const uint32_t a[4],
                                         uint32_t b0, uint32_t b1) {
    asm volatile(
        "mma.sync.aligned.m16n8k16.row.col.f32.bf16.bf16.f32 "
        "{%0,%1,%2,%3}, {%4,%5,%6,%7}, {%8,%9}, {%0,%1,%2,%3};"
        : "+f"(c[0]), "+f"(c[1]), "+f"(c[2]), "+f"(c[3])
        : "r"(a[0]), "r"(a[1]), "r"(a[2]), "r"(a[3]), "r"(b0), "r"(b1));
}

#define SPAD 40  // padded row stride (bf16 elems): bank = (r*20+t)%32, conflict-free

__global__ __launch_bounds__(256) void gemm_bf16x3(
    const float* __restrict__ A, const float* __restrict__ W,
    float* __restrict__ C, int M, int N, int K, const float* __restrict__ bias)
{
    __shared__ __align__(16) __nv_bfloat16 Ash[128][SPAD];
    __shared__ __align__(16) __nv_bfloat16 Asl[128][SPAD];
    __shared__ __align__(16) __nv_bfloat16 Bsh[128][SPAD];
    __shared__ __align__(16) __nv_bfloat16 Bsl[128][SPAD];

    const int tid  = threadIdx.x;
    const int lane = tid & 31;
    const int warp = tid >> 5;
    const int warpM = warp >> 1;   // 0..3  (32 rows each)
    const int warpN = warp & 1;    // 0..1  (64 cols each)
    const int bm = blockIdx.y * 128;
    const int bn = blockIdx.x * 128;

    float acc[2][8][4];
#pragma unroll
    for (int i = 0; i < 2; i++)
#pragma unroll
        for (int j = 0; j < 8; j++)
#pragma unroll
            for (int l = 0; l < 4; l++) acc[i][j][l] = 0.f;

    // ldmatrix lane addressing (constant across k-tiles)
    const int aRow = warpM * 32 + (lane & 7) + ((lane & 8) ? 8 : 0);
    const int aColOff = (lane & 16) ? 8 : 0;
    const int bRowOff = (lane & 7) + ((lane & 16) ? 8 : 0);
    const int bColOff = (lane & 8) ? 8 : 0;

    for (int k0 = 0; k0 < K; k0 += 32) {
        // ---- stage A tile (128 x 32) ----
#pragma unroll
        for (int i = 0; i < 4; i++) {
            int idx = tid + i * 256;             // 0..1023
            int row = idx >> 3, c4 = (idx & 7) * 4;
            float4 v = *(const float4*)(A + (size_t)(bm + row) * K + k0 + c4);
            float f[4] = {v.x, v.y, v.z, v.w};
            __nv_bfloat162 h0, h1, l0, l1;
            __nv_bfloat16 h, l;
            h = __float2bfloat16_rn(f[0]); l = __float2bfloat16_rn(f[0] - __bfloat162float(h)); h0.x = h; l0.x = l;
            h = __float2bfloat16_rn(f[1]); l = __float2bfloat16_rn(f[1] - __bfloat162float(h)); h0.y = h; l0.y = l;
            h = __float2bfloat16_rn(f[2]); l = __float2bfloat16_rn(f[2] - __bfloat162float(h)); h1.x = h; l1.x = l;
            h = __float2bfloat16_rn(f[3]); l = __float2bfloat16_rn(f[3] - __bfloat162float(h)); h1.y = h; l1.y = l;
            *(__nv_bfloat162*)&Ash[row][c4]     = h0;
            *(__nv_bfloat162*)&Ash[row][c4 + 2] = h1;
            *(__nv_bfloat162*)&Asl[row][c4]     = l0;
            *(__nv_bfloat162*)&Asl[row][c4 + 2] = l1;
        }
        // ---- stage B tile (32 x 128) transposed to [n][k] ----
#pragma unroll
        for (int i = 0; i < 4; i++) {
            int idx = tid + i * 256;
            int kr = idx >> 5, c4 = (idx & 31) * 4;
            float4 v = *(const float4*)(W + (size_t)(k0 + kr) * N + bn + c4);
            float f[4] = {v.x, v.y, v.z, v.w};
#pragma unroll
            for (int j = 0; j < 4; j++) {
                __nv_bfloat16 h = __float2bfloat16_rn(f[j]);
                __nv_bfloat16 l = __float2bfloat16_rn(f[j] - __bfloat162float(h));
                Bsh[c4 + j][kr] = h;
                Bsl[c4 + j][kr] = l;
            }
        }
        __syncthreads();

        // ---- compute: 2 k16 steps ----
#pragma unroll
        for (int ks = 0; ks < 2; ks++) {
            uint32_t ah[2][4], al[2][4];
#pragma unroll
            for (int mi = 0; mi < 2; mi++) {
                const int r = aRow + mi * 16;
                const int c = ks * 16 + aColOff;
                ldsm_x4(ah[mi], &Ash[r][c]);
                ldsm_x4(al[mi], &Asl[r][c]);
            }
            uint32_t bh[4][4], bl[4][4];
#pragma unroll
            for (int n2 = 0; n2 < 4; n2++) {
                const int nr = warpN * 64 + n2 * 16 + bRowOff;
                const int c = ks * 16 + bColOff;
                ldsm_x4(bh[n2], &Bsh[nr][c]);
                ldsm_x4(bl[n2], &Bsl[nr][c]);
            }
#pragma unroll
            for (int mi = 0; mi < 2; mi++)
#pragma unroll
                for (int n2 = 0; n2 < 4; n2++) {
                    mma16816(acc[mi][2*n2],   ah[mi], bh[n2][0], bh[n2][1]);
                    mma16816(acc[mi][2*n2+1], ah[mi], bh[n2][2], bh[n2][3]);
                    mma16816(acc[mi][2*n2],   ah[mi], bl[n2][0], bl[n2][1]);
                    mma16816(acc[mi][2*n2+1], ah[mi], bl[n2][2], bl[n2][3]);
                    mma16816(acc[mi][2*n2],   al[mi], bh[n2][0], bh[n2][1]);
                    mma16816(acc[mi][2*n2+1], al[mi], bh[n2][2], bh[n2][3]);
                }
        }
        __syncthreads();
    }

    // ---- epilogue ----
    const int g = lane >> 2, t = lane & 3;
#pragma unroll
    for (int mi = 0; mi < 2; mi++) {
        int row = bm + warpM * 32 + mi * 16 + g;
#pragma unroll
        for (int ni = 0; ni < 8; ni++) {
            int col = bn + warpN * 64 + ni * 8 + t * 2;
            float b0 = 0.f, b1 = 0.f;
            if (bias) { b0 = bias[col]; b1 = bias[col + 1]; }
            float2 v0 = {acc[mi][ni][0] + b0, acc[mi][ni][1] + b1};
            float2 v1 = {acc[mi][ni][2] + b0, acc[mi][ni][3] + b1};
            *(float2*)(C + (size_t)row * N + col)       = v0;
            *(float2*)(C + (size_t)(row + 8) * N + col) = v1;
        }
    }
}

// ---------------------------------------------------------------------------
// Softmax over head_dim (64) for k, in place. One warp per (b,n,h) row.
// ---------------------------------------------------------------------------
__global__ __launch_bounds__(256) void softmax_k_kernel()
{
    int tid = threadIdx.x;
    int warp = tid >> 5, lane = tid & 31;
    long r = (long)blockIdx.x * 8 + warp;
    int bn = (int)(r / HEADS), h = (int)(r % HEADS);
    float* p = g_kv + (size_t)bn * EDIM + h * HD;

    float v0 = p[lane], v1 = p[lane + 32];
    float m = fmaxf(v0, v1);
#pragma unroll
    for (int o = 16; o > 0; o >>= 1) m = fmaxf(m, __shfl_xor_sync(0xffffffffu, m, o));
    float e0 = expf(v0 - m), e1 = expf(v1 - m);
    float s = e0 + e1;
#pragma unroll
    for (int o = 16; o > 0; o >>= 1) s += __shfl_xor_sync(0xffffffffu, s, o);
    float inv = 1.f / s;
    p[lane] = e0 * inv;
    p[lane + 32] = e1 * inv;
}

// ---------------------------------------------------------------------------
// ktv partials: split N into KTV_SPLIT chunks for occupancy.
// block = (bh, split). Deterministic two-phase (no atomics).
// ---------------------------------------------------------------------------
__global__ __launch_bounds__(256) void ktv_part_kernel()
{
    int bh = blockIdx.x;            // 0..95
    int s  = blockIdx.y;            // 0..KTV_SPLIT-1
    int b = bh / HEADS, h = bh % HEADS;
    const int chunk = NN / KTV_SPLIT;            // 256
    const float* ksp = g_kv + (size_t)b * NN * EDIM + h * HD + (size_t)s * chunk * EDIM;
    const float* vp  = ksp + DIMV;

    __shared__ float Ks[32][64];
    __shared__ float Vs[32][64];

    int tid = threadIdx.x;
    int td = tid & 15, te = tid >> 4;
    float acc[4][4];
#pragma unroll
    for (int i = 0; i < 4; i++)
#pragma unroll
        for (int j = 0; j < 4; j++) acc[i][j] = 0.f;

    for (int n0 = 0; n0 < chunk; n0 += 32) {
#pragma unroll
        for (int i = 0; i < 2; i++) {
            int idx4 = tid + i * 256;
            int nl = idx4 >> 4, d4 = (idx4 & 15) * 4;
            *(float4*)&Ks[nl][d4] = *(const float4*)(ksp + (size_t)(n0 + nl) * EDIM + d4);
            *(float4*)&Vs[nl][d4] = *(const float4*)(vp  + (size_t)(n0 + nl) * EDIM + d4);
        }
        __syncthreads();
#pragma unroll 8
        for (int n = 0; n < 32; n++) {
            float a0[4], b0[4];
            *(float4*)a0 = *(const float4*)&Ks[n][td * 4];
            *(float4*)b0 = *(const float4*)&Vs[n][te * 4];
#pragma unroll
            for (int i = 0; i < 4; i++)
#pragma unroll
                for (int j = 0; j < 4; j++)
                    acc[i][j] += a0[i] * b0[j];
        }
        __syncthreads();
    }

    float* out = g_ktvp + ((size_t)s * 96 + bh) * HD * HD;
#pragma unroll
    for (int i = 0; i < 4; i++) {
        float4 v;
        v.x = acc[i][0]; v.y = acc[i][1]; v.z = acc[i][2]; v.w = acc[i][3];
        *(float4*)&out[(td * 4 + i) * HD + te * 4] = v;
    }
}

__global__ void ktv_reduce_kernel()
{
    int idx = blockIdx.x * 256 + threadIdx.x;    // < 96*4096
    float s = 0.f;
#pragma unroll
    for (int i = 0; i < KTV_SPLIT; i++)
        s += g_ktvp[(size_t)i * 96 * HD * HD + idx];
    g_ktv[idx] = s;
}

// ---------------------------------------------------------------------------
// ektv[b,j,d,e] head-expansion (roll by -32 over the (h,e) flat axis).
// ---------------------------------------------------------------------------
__global__ void build_ektv_kernel()
{
    int idx = blockIdx.x * 256 + threadIdx.x;
    int e = idx & 63;
    int d = (idx >> 6) & 63;
    int bj = idx >> 12;
    int j = bj % 24, b = bj / 24;
    float val;
    if (j < 12) {
        val = g_ktv[(((size_t)(b * 12 + j) * 64) + d) * 64 + e];
    } else {
        int c = (j - 12) * 64 + e + 32;
        if (c >= 768) c -= 768;
        int hp = c >> 6, ep = c & 63;
        val = g_ktv[(((size_t)(b * 12 + hp) * 64) + d) * 64 + ep];
    }
    g_ektv[idx] = val;
}

// ---------------------------------------------------------------------------
// attn: y[b, n, j*64+e] = scale * sum_d eq[b,j,n,d] * ektv[b,j,d,e]
// ---------------------------------------------------------------------------
__global__ __launch_bounds__(256) void attn_kernel()
{
    int b = blockIdx.z, j = blockIdx.y, n0 = blockIdx.x * 64;
    __shared__ float Es[64][64];
    __shared__ float Qs[64][64];
    int tid = threadIdx.x;

    const float* ep = g_ektv + (size_t)((b * 24 + j) * 64) * 64;
#pragma unroll
    for (int i = 0; i < 4; i++) {
        int idx4 = tid + i * 256;
        *(float4*)&Es[idx4 >> 4][(idx4 & 15) * 4] = *(const float4*)(ep + idx4 * 4);
    }

    int qbase = (j < 12) ? j * 64 : ((j - 12) * 64 + 32);
    const float* qp = g_q + (size_t)(b * NN + n0) * DIMV;
#pragma unroll
    for (int i = 0; i < 4; i++) {
        int idx4 = tid + i * 256;
        int nl = idx4 >> 4, d4 = (idx4 & 15) * 4;
        int c = qbase + d4;
        if (c >= 768) c -= 768;
        *(float4*)&Qs[nl][d4] = *(const float4*)(qp + (size_t)nl * DIMV + c);
    }
    __syncthreads();

    int r0 = (tid >> 4) * 4, e0 = (tid & 15) * 4;
    float acc[4][4];
#pragma unroll
    for (int i = 0; i < 4; i++)
#pragma unroll
        for (int jj = 0; jj < 4; jj++) acc[i][jj] = 0.f;

#pragma unroll 8
    for (int d = 0; d < 64; d++) {
        float a0[4], b0[4];
        a0[0] = Qs[r0 + 0][d]; a0[1] = Qs[r0 + 1][d];
        a0[2] = Qs[r0 + 2][d]; a0[3] = Qs[r0 + 3][d];
        *(float4*)b0 = *(const float4*)&Es[d][e0];
#pragma unroll
        for (int i = 0; i < 4; i++)
#pragma unroll
            for (int jj = 0; jj < 4; jj++)
                acc[i][jj] += a0[i] * b0[jj];
    }

    const float scale = 0.125f;
#pragma unroll
    for (int i = 0; i < 4; i++) {
        float4 v;
        v.x = scale * acc[i][0]; v.y = scale * acc[i][1];
        v.z = scale * acc[i][2]; v.w = scale * acc[i][3];
        *(float4*)(g_y + (size_t)(b * NN + n0 + r0 + i) * EDIM + j * 64 + e0) = v;
    }
}

// ---------------------------------------------------------------------------
// LePE depthwise 3x3 conv accumulated into g_y (+bias).
// ---------------------------------------------------------------------------
__global__ __launch_bounds__(256) void lepe_kernel(
    const float* __restrict__ w_lepe, const float* __restrict__ b_lepe)
{
    __shared__ float In[18][18][32];
    __shared__ float Wt[32][9];
    __shared__ float Bsh[32];

    int b = blockIdx.z;
    int chunk = blockIdx.y;
    int tile = blockIdx.x;
    int c0 = chunk * 32;
    int j = c0 >> 6, dlo = c0 & 63;
    int base = (j < 12) ? c0 : ((j - 12) * 64 + 32 + dlo);
    if (base >= 768) base -= 768;
    int ty0 = (tile >> 2) * 16, tx0 = (tile & 3) * 16;
    int tid = threadIdx.x;

    for (int idx = tid; idx < 32 * 9; idx += 256)
        Wt[idx / 9][idx % 9] = w_lepe[c0 * 9 + idx];
    if (tid < 32) Bsh[tid] = b_lepe[c0 + tid];

    const float* qb = g_q + (size_t)b * NN * DIMV + base;
    for (int idx = tid; idx < 18 * 18 * 32; idx += 256) {
        int c = idx & 31;
        int sp = idx >> 5;
        int sy = sp / 18, sx = sp - sy * 18;
        int hh = ty0 + sy - 1, ww = tx0 + sx - 1;
        float v = 0.f;
        if (hh >= 0 && hh < 64 && ww >= 0 && ww < 64)
            v = qb[(size_t)(hh * 64 + ww) * DIMV + c];
        In[sy][sx][c] = v;
    }
    __syncthreads();

    int c = tid & 31, sg = tid >> 5;
    float* yb = g_y + (size_t)b * NN * EDIM + c0 + c;
#pragma unroll 4
    for (int s = 0; s < 32; s++) {
        int sp = sg * 32 + s;
        int sy = sp >> 4, sx = sp & 15;
        float sum = Bsh[c];
#pragma unroll
        for (int ky = 0; ky < 3; ky++)
#pragma unroll
            for (int kx = 0; kx < 3; kx++)
                sum += Wt[c][ky * 3 + kx] * In[sy + ky][sx + kx][c];
        int n = (ty0 + sy) * 64 + (tx0 + sx);
        yb[(size_t)n * EDIM] += sum;
    }
}

// ---------------------------------------------------------------------------
extern "C" void kernel_launch(void* const* d_in, const int* in_sizes, int n_in,
                              void* d_out, int out_size)
{
    const float* x      = (const float*)d_in[0];
    const float* w_q    = (const float*)d_in[1];
    const float* w_kv   = (const float*)d_in[2];
    const float* w_proj = (const float*)d_in[3];
    const float* b_proj = (const float*)d_in[4];
    const float* w_lepe = (const float*)d_in[5];
    const float* b_lepe = (const float*)d_in[6];
    float* out = (float*)d_out;

    float* q = nullptr; float* kv = nullptr; float* y = nullptr;
    cudaGetSymbolAddress((void**)&q,  g_q);
    cudaGetSymbolAddress((void**)&kv, g_kv);
    cudaGetSymbolAddress((void**)&y,  g_y);

    // 1-2: input projections (tensor cores, bf16x3)
    gemm_bf16x3<<<dim3(DIMV / 128, MTOT / 128), 256>>>(x, w_q,  q,  MTOT, DIMV, DIMV, nullptr);
    gemm_bf16x3<<<dim3(EDIM / 128, MTOT / 128), 256>>>(x, w_kv, kv, MTOT, EDIM, DIMV, nullptr);

    // 3: softmax over head_dim on k
    softmax_k_kernel<<<(MTOT * HEADS) / 8, 256>>>();

    // 4: K^T V per (b,h), split over N + reduce
    ktv_part_kernel<<<dim3(BB * HEADS, KTV_SPLIT), 256>>>();
    ktv_reduce_kernel<<<(BB * HEADS * HD * HD) / 256, 256>>>();

    // 5: head-expand ktv
    build_ektv_kernel<<<(BB * 24 * HD * HD) / 256, 256>>>();

    // 6: attn = eq @ ektv (scaled) -> y
    attn_kernel<<<dim3(NN / 64, 24, BB), 256>>>();

    // 7: LePE conv accumulated into y
    lepe_kernel<<<dim3(16, EDIM / 32, BB), 256>>>(w_lepe, b_lepe);

    // 8: output projection + bias
    gemm_bf16x3<<<dim3(DIMV / 128, MTOT / 128), 256>>>(y, w_proj, out, MTOT, DIMV, EDIM, b_proj);
}

// round 5
// speedup vs baseline: 2.2282x; 1.8995x over previous
#include <cuda_runtime.h>
#include <cuda_bf16.h>
#include <cstdint>

// Problem constants
#define BB    8
#define NN    4096
#define DIMV  768
#define HEADS 12
#define HD    64
#define EDIM  1536
#define MTOT  (BB*NN)   // 32768
#define KTV_SPLIT 16

// Scratch (static device allocations)
__device__ float g_q   [(size_t)MTOT * DIMV];
__device__ float g_kv  [(size_t)MTOT * EDIM];
__device__ float g_y   [(size_t)MTOT * EDIM];
__device__ float g_ktv [BB * HEADS * HD * HD];
__device__ float g_ktvp[(size_t)KTV_SPLIT * BB * HEADS * HD * HD];
__device__ float g_ektv[BB * 2*HEADS * HD * HD];

// bf16 hi/lo split operands
__device__ __nv_bfloat16 g_xh[(size_t)MTOT * DIMV];
__device__ __nv_bfloat16 g_xl[(size_t)MTOT * DIMV];
__device__ __nv_bfloat16 g_yh[(size_t)MTOT * EDIM];
__device__ __nv_bfloat16 g_yl[(size_t)MTOT * EDIM];
// weights transposed to [N][K] + split
__device__ __nv_bfloat16 g_wqh [DIMV * DIMV];
__device__ __nv_bfloat16 g_wql [DIMV * DIMV];
__device__ __nv_bfloat16 g_wkvh[EDIM * DIMV];
__device__ __nv_bfloat16 g_wkvl[EDIM * DIMV];
__device__ __nv_bfloat16 g_wph [DIMV * EDIM];
__device__ __nv_bfloat16 g_wpl [DIMV * EDIM];

// ---------------------------------------------------------------------------
// MMA / cp.async helpers
// ---------------------------------------------------------------------------
__device__ __forceinline__ void ldsm_x4(uint32_t r[4], const __nv_bfloat16* p) {
    uint32_t a = (uint32_t)__cvta_generic_to_shared(p);
    asm volatile("ldmatrix.sync.aligned.m8n8.x4.shared.b16 {%0,%1,%2,%3}, [%4];"
                 : "=r"(r[0]), "=r"(r[1]), "=r"(r[2]), "=r"(r[3]) : "r"(a));
}
__device__ __forceinline__ void mma16816(float c[4], const uint32_t a[4],
                                         uint32_t b0, uint32_t b1) {
    asm volatile(
        "mma.sync.aligned.m16n8k16.row.col.f32.bf16.bf16.f32 "
        "{%0,%1,%2,%3}, {%4,%5,%6,%7}, {%8,%9}, {%0,%1,%2,%3};"
        : "+f"(c[0]), "+f"(c[1]), "+f"(c[2]), "+f"(c[3])
        : "r"(a[0]), "r"(a[1]), "r"(a[2]), "r"(a[3]), "r"(b0), "r"(b1));
}
__device__ __forceinline__ void cp_async16(void* smem_dst, const void* gsrc) {
    uint32_t a = (uint32_t)__cvta_generic_to_shared(smem_dst);
    asm volatile("cp.async.cg.shared.global [%0], [%1], 16;" :: "r"(a), "l"(gsrc));
}
#define CP_COMMIT() asm volatile("cp.async.commit_group;" ::: "memory")
#define CP_WAIT0()  asm volatile("cp.async.wait_group 0;" ::: "memory")

#define SPAD   40                      // padded row stride in bf16 (80 B, 16B-mult)
#define PIECE  (128 * SPAD * 2)        // 10240 B  (one 128x32 bf16 tile, padded)
#define STAGE  (4 * PIECE)             // Ah, Al, Bh, Bl
#define GEMM_DSMEM (2 * STAGE)         // 81920 B

// ---------------------------------------------------------------------------
// bf16x3 tensor-core GEMM, pre-split operands, cp.async double-buffered.
// C[M,N] = (Ah+Al)[M,K] @ (Bh+Bl)[N,K]^T (+bias).  128x128 tile, BK=32.
// ---------------------------------------------------------------------------
__global__ __launch_bounds__(256, 2) void gemm_mma(
    const __nv_bfloat16* __restrict__ Ah, const __nv_bfloat16* __restrict__ Al,
    const __nv_bfloat16* __restrict__ Bh, const __nv_bfloat16* __restrict__ Bl,
    float* __restrict__ C, int M, int N, int K, const float* __restrict__ bias)
{
    extern __shared__ char smem[];

    const int tid  = threadIdx.x;
    const int lane = tid & 31;
    const int warp = tid >> 5;
    const int warpM = warp >> 1;
    const int warpN = warp & 1;
    const int bm = blockIdx.y * 128;
    const int bn = blockIdx.x * 128;

    float acc[2][8][4];
#pragma unroll
    for (int i = 0; i < 2; i++)
#pragma unroll
        for (int j = 0; j < 8; j++)
#pragma unroll
            for (int l = 0; l < 4; l++) acc[i][j][l] = 0.f;

    const int aRow = warpM * 32 + (lane & 7) + ((lane & 8) ? 8 : 0);
    const int aColOff = (lane & 16) ? 8 : 0;
    const int bRowOff = (lane & 7) + ((lane & 16) ? 8 : 0);
    const int bColOff = (lane & 8) ? 8 : 0;

    const __nv_bfloat16* srcs[4] = {Ah, Al, Bh, Bl};
    const int rowbase[4] = {bm, bm, bn, bn};
    const int row = tid >> 1;                  // 0..127
    const int ch0 = (tid & 1) * 2;             // chunks {0,1} or {2,3}

    // stage kt's 4 tiles (8 x 16B per thread)
    auto issue_stage = [&](int kt) {
        char* st = smem + (kt & 1) * STAGE;
        const int k0 = kt << 5;
#pragma unroll
        for (int p = 0; p < 4; p++) {
            const __nv_bfloat16* src = srcs[p] + (size_t)(rowbase[p] + row) * K + k0;
#pragma unroll
            for (int c = 0; c < 2; c++) {
                int ch = ch0 + c;
                cp_async16(st + p * PIECE + (row * SPAD + ch * 8) * 2, src + ch * 8);
            }
        }
    };

    const int NK = K >> 5;
    issue_stage(0);
    CP_COMMIT();

    for (int kt = 0; kt < NK; kt++) {
        CP_WAIT0();
        __syncthreads();
        if (kt + 1 < NK) issue_stage(kt + 1);
        CP_COMMIT();

        const char* st = smem + (kt & 1) * STAGE;
        const __nv_bfloat16* pAh = (const __nv_bfloat16*)(st);
        const __nv_bfloat16* pAl = (const __nv_bfloat16*)(st + PIECE);
        const __nv_bfloat16* pBh = (const __nv_bfloat16*)(st + 2 * PIECE);
        const __nv_bfloat16* pBl = (const __nv_bfloat16*)(st + 3 * PIECE);

#pragma unroll
        for (int ks = 0; ks < 2; ks++) {
            const int ac = ks * 16 + aColOff;
            const int bc = ks * 16 + bColOff;
            uint32_t ah[2][4], al[2][4];
#pragma unroll
            for (int mi = 0; mi < 2; mi++) {
                ldsm_x4(ah[mi], pAh + (aRow + mi * 16) * SPAD + ac);
                ldsm_x4(al[mi], pAl + (aRow + mi * 16) * SPAD + ac);
            }
#pragma unroll
            for (int n2 = 0; n2 < 4; n2++) {
                const int nr = warpN * 64 + n2 * 16 + bRowOff;
                uint32_t bh[4], bl[4];
                ldsm_x4(bh, pBh + nr * SPAD + bc);
                ldsm_x4(bl, pBl + nr * SPAD + bc);
#pragma unroll
                for (int mi = 0; mi < 2; mi++) {
                    mma16816(acc[mi][2*n2],   ah[mi], bh[0], bh[1]);
                    mma16816(acc[mi][2*n2+1], ah[mi], bh[2], bh[3]);
                    mma16816(acc[mi][2*n2],   ah[mi], bl[0], bl[1]);
                    mma16816(acc[mi][2*n2+1], ah[mi], bl[2], bl[3]);
                    mma16816(acc[mi][2*n2],   al[mi], bh[0], bh[1]);
                    mma16816(acc[mi][2*n2+1], al[mi], bh[2], bh[3]);
                }
            }
        }
        __syncthreads();
    }

    // epilogue: direct register -> global stores
    const int g = lane >> 2, t = lane & 3;
#pragma unroll
    for (int mi = 0; mi < 2; mi++) {
        int r = bm + warpM * 32 + mi * 16 + g;
#pragma unroll
        for (int ni = 0; ni < 8; ni++) {
            int col = bn + warpN * 64 + ni * 8 + t * 2;
            float b0 = 0.f, b1 = 0.f;
            if (bias) { b0 = bias[col]; b1 = bias[col + 1]; }
            float2 v0 = {acc[mi][ni][0] + b0, acc[mi][ni][1] + b1};
            float2 v1 = {acc[mi][ni][2] + b0, acc[mi][ni][3] + b1};
            *(float2*)(C + (size_t)r * N + col)       = v0;
            *(float2*)(C + (size_t)(r + 8) * N + col) = v1;
        }
    }
}

// ---------------------------------------------------------------------------
// split x (fp32 -> bf16 hi/lo)
// ---------------------------------------------------------------------------
__global__ __launch_bounds__(256) void split_x_kernel(const float* __restrict__ x)
{
    int i = blockIdx.x * 256 + threadIdx.x;
    float4 v = ((const float4*)x)[i];
    float f[4] = {v.x, v.y, v.z, v.w};
    __nv_bfloat162 h01, h23, l01, l23;
    __nv_bfloat16 h, l;
    h = __float2bfloat16_rn(f[0]); l = __float2bfloat16_rn(f[0] - __bfloat162float(h)); h01.x = h; l01.x = l;
    h = __float2bfloat16_rn(f[1]); l = __float2bfloat16_rn(f[1] - __bfloat162float(h)); h01.y = h; l01.y = l;
    h = __float2bfloat16_rn(f[2]); l = __float2bfloat16_rn(f[2] - __bfloat162float(h)); h23.x = h; l23.x = l;
    h = __float2bfloat16_rn(f[3]); l = __float2bfloat16_rn(f[3] - __bfloat162float(h)); h23.y = h; l23.y = l;
    ((__nv_bfloat162*)g_xh)[2 * i] = h01; ((__nv_bfloat162*)g_xh)[2 * i + 1] = h23;
    ((__nv_bfloat162*)g_xl)[2 * i] = l01; ((__nv_bfloat162*)g_xl)[2 * i + 1] = l23;
}

// ---------------------------------------------------------------------------
// weight transpose + split: W[K][N] -> Th/Tl[N][K]
// ---------------------------------------------------------------------------
__global__ __launch_bounds__(256) void wsplit_kernel(
    const float* __restrict__ W, __nv_bfloat16* __restrict__ Th,
    __nv_bfloat16* __restrict__ Tl, int K, int N)
{
    __shared__ float t[32][33];
    int n0 = blockIdx.x * 32, k0 = blockIdx.y * 32;
    int tx = threadIdx.x & 31, ty = threadIdx.x >> 5;
#pragma unroll
    for (int i = 0; i < 4; i++)
        t[ty + i * 8][tx] = W[(size_t)(k0 + ty + i * 8) * N + n0 + tx];
    __syncthreads();
#pragma unroll
    for (int i = 0; i < 4; i++) {
        float f = t[tx][ty + i * 8];
        __nv_bfloat16 h = __float2bfloat16_rn(f);
        __nv_bfloat16 l = __float2bfloat16_rn(f - __bfloat162float(h));
        Th[(size_t)(n0 + ty + i * 8) * K + k0 + tx] = h;
        Tl[(size_t)(n0 + ty + i * 8) * K + k0 + tx] = l;
    }
}

// ---------------------------------------------------------------------------
// Softmax over head_dim (64) for k, in place.
// ---------------------------------------------------------------------------
__global__ __launch_bounds__(256) void softmax_k_kernel()
{
    int tid = threadIdx.x;
    int warp = tid >> 5, lane = tid & 31;
    long r = (long)blockIdx.x * 8 + warp;
    int bn = (int)(r / HEADS), h = (int)(r % HEADS);
    float* p = g_kv + (size_t)bn * EDIM + h * HD;

    float v0 = p[lane], v1 = p[lane + 32];
    float m = fmaxf(v0, v1);
#pragma unroll
    for (int o = 16; o > 0; o >>= 1) m = fmaxf(m, __shfl_xor_sync(0xffffffffu, m, o));
    float e0 = expf(v0 - m), e1 = expf(v1 - m);
    float s = e0 + e1;
#pragma unroll
    for (int o = 16; o > 0; o >>= 1) s += __shfl_xor_sync(0xffffffffu, s, o);
    float inv = 1.f / s;
    p[lane] = e0 * inv;
    p[lane + 32] = e1 * inv;
}

// ---------------------------------------------------------------------------
// ktv partials + reduce
// ---------------------------------------------------------------------------
__global__ __launch_bounds__(256) void ktv_part_kernel()
{
    int bh = blockIdx.x, s = blockIdx.y;
    int b = bh / HEADS, h = bh % HEADS;
    const int chunk = NN / KTV_SPLIT;
    const float* ksp = g_kv + (size_t)b * NN * EDIM + h * HD + (size_t)s * chunk * EDIM;
    const float* vp  = ksp + DIMV;

    __shared__ float Ks[32][64];
    __shared__ float Vs[32][64];

    int tid = threadIdx.x;
    int td = tid & 15, te = tid >> 4;
    float acc[4][4];
#pragma unroll
    for (int i = 0; i < 4; i++)
#pragma unroll
        for (int j = 0; j < 4; j++) acc[i][j] = 0.f;

    for (int n0 = 0; n0 < chunk; n0 += 32) {
#pragma unroll
        for (int i = 0; i < 2; i++) {
            int idx4 = tid + i * 256;
            int nl = idx4 >> 4, d4 = (idx4 & 15) * 4;
            *(float4*)&Ks[nl][d4] = *(const float4*)(ksp + (size_t)(n0 + nl) * EDIM + d4);
            *(float4*)&Vs[nl][d4] = *(const float4*)(vp  + (size_t)(n0 + nl) * EDIM + d4);
        }
        __syncthreads();
#pragma unroll 8
        for (int n = 0; n < 32; n++) {
            float a0[4], b0[4];
            *(float4*)a0 = *(const float4*)&Ks[n][td * 4];
            *(float4*)b0 = *(const float4*)&Vs[n][te * 4];
#pragma unroll
            for (int i = 0; i < 4; i++)
#pragma unroll
                for (int j = 0; j < 4; j++)
                    acc[i][j] += a0[i] * b0[j];
        }
        __syncthreads();
    }

    float* out = g_ktvp + ((size_t)s * 96 + bh) * HD * HD;
#pragma unroll
    for (int i = 0; i < 4; i++) {
        float4 v;
        v.x = acc[i][0]; v.y = acc[i][1]; v.z = acc[i][2]; v.w = acc[i][3];
        *(float4*)&out[(td * 4 + i) * HD + te * 4] = v;
    }
}

__global__ void ktv_reduce_kernel()
{
    int idx = blockIdx.x * 256 + threadIdx.x;
    float s = 0.f;
#pragma unroll
    for (int i = 0; i < KTV_SPLIT; i++)
        s += g_ktvp[(size_t)i * 96 * HD * HD + idx];
    g_ktv[idx] = s;
}

// ---------------------------------------------------------------------------
// ektv head-expansion
// ---------------------------------------------------------------------------
__global__ void build_ektv_kernel()
{
    int idx = blockIdx.x * 256 + threadIdx.x;
    int e = idx & 63;
    int d = (idx >> 6) & 63;
    int bj = idx >> 12;
    int j = bj % 24, b = bj / 24;
    float val;
    if (j < 12) {
        val = g_ktv[(((size_t)(b * 12 + j) * 64) + d) * 64 + e];
    } else {
        int c = (j - 12) * 64 + e + 32;
        if (c >= 768) c -= 768;
        int hp = c >> 6, ep = c & 63;
        val = g_ktv[(((size_t)(b * 12 + hp) * 64) + d) * 64 + ep];
    }
    g_ektv[idx] = val;
}

// ---------------------------------------------------------------------------
// attn: y = scale * eq @ ektv  (fp32 out)
// ---------------------------------------------------------------------------
__global__ __launch_bounds__(256) void attn_kernel()
{
    int b = blockIdx.z, j = blockIdx.y, n0 = blockIdx.x * 64;
    __shared__ float Es[64][64];
    __shared__ float Qs[64][64];
    int tid = threadIdx.x;

    const float* ep = g_ektv + (size_t)((b * 24 + j) * 64) * 64;
#pragma unroll
    for (int i = 0; i < 4; i++) {
        int idx4 = tid + i * 256;
        *(float4*)&Es[idx4 >> 4][(idx4 & 15) * 4] = *(const float4*)(ep + idx4 * 4);
    }

    int qbase = (j < 12) ? j * 64 : ((j - 12) * 64 + 32);
    const float* qp = g_q + (size_t)(b * NN + n0) * DIMV;
#pragma unroll
    for (int i = 0; i < 4; i++) {
        int idx4 = tid + i * 256;
        int nl = idx4 >> 4, d4 = (idx4 & 15) * 4;
        int c = qbase + d4;
        if (c >= 768) c -= 768;
        *(float4*)&Qs[nl][d4] = *(const float4*)(qp + (size_t)nl * DIMV + c);
    }
    __syncthreads();

    int r0 = (tid >> 4) * 4, e0 = (tid & 15) * 4;
    float acc[4][4];
#pragma unroll
    for (int i = 0; i < 4; i++)
#pragma unroll
        for (int jj = 0; jj < 4; jj++) acc[i][jj] = 0.f;

#pragma unroll 8
    for (int d = 0; d < 64; d++) {
        float a0[4], b0[4];
        a0[0] = Qs[r0 + 0][d]; a0[1] = Qs[r0 + 1][d];
        a0[2] = Qs[r0 + 2][d]; a0[3] = Qs[r0 + 3][d];
        *(float4*)b0 = *(const float4*)&Es[d][e0];
#pragma unroll
        for (int i = 0; i < 4; i++)
#pragma unroll
            for (int jj = 0; jj < 4; jj++)
                acc[i][jj] += a0[i] * b0[jj];
    }

    const float scale = 0.125f;
#pragma unroll
    for (int i = 0; i < 4; i++) {
        float4 v;
        v.x = scale * acc[i][0]; v.y = scale * acc[i][1];
        v.z = scale * acc[i][2]; v.w = scale * acc[i][3];
        *(float4*)(g_y + (size_t)(b * NN + n0 + r0 + i) * EDIM + j * 64 + e0) = v;
    }
}

// ---------------------------------------------------------------------------
// LePE conv + fuse: (yh,yl) = split(y_attn + conv(q) + bias)
// ---------------------------------------------------------------------------
__global__ __launch_bounds__(256) void lepe_kernel(
    const float* __restrict__ w_lepe, const float* __restrict__ b_lepe)
{
    __shared__ float In[18][18][32];
    __shared__ float Wt[32][9];
    __shared__ float Bsh[32];

    int b = blockIdx.z;
    int chunk = blockIdx.y;
    int tile = blockIdx.x;
    int c0 = chunk * 32;
    int j = c0 >> 6, dlo = c0 & 63;
    int base = (j < 12) ? c0 : ((j - 12) * 64 + 32 + dlo);
    if (base >= 768) base -= 768;
    int ty0 = (tile >> 2) * 16, tx0 = (tile & 3) * 16;
    int tid = threadIdx.x;

    for (int idx = tid; idx < 32 * 9; idx += 256)
        Wt[idx / 9][idx % 9] = w_lepe[c0 * 9 + idx];
    if (tid < 32) Bsh[tid] = b_lepe[c0 + tid];

    const float* qb = g_q + (size_t)b * NN * DIMV + base;
    for (int idx = tid; idx < 18 * 18 * 32; idx += 256) {
        int c = idx & 31;
        int sp = idx >> 5;
        int sy = sp / 18, sx = sp - sy * 18;
        int hh = ty0 + sy - 1, ww = tx0 + sx - 1;
        float v = 0.f;
        if (hh >= 0 && hh < 64 && ww >= 0 && ww < 64)
            v = qb[(size_t)(hh * 64 + ww) * DIMV + c];
        In[sy][sx][c] = v;
    }
    __syncthreads();

    int c = tid & 31, sg = tid >> 5;
    const float* yb = g_y + (size_t)b * NN * EDIM + c0 + c;
    __nv_bfloat16* yhb = g_yh + (size_t)b * NN * EDIM + c0 + c;
    __nv_bfloat16* ylb = g_yl + (size_t)b * NN * EDIM + c0 + c;
#pragma unroll 4
    for (int s = 0; s < 32; s++) {
        int sp = sg * 32 + s;
        int sy = sp >> 4, sx = sp & 15;
        float sum = Bsh[c];
#pragma unroll
        for (int ky = 0; ky < 3; ky++)
#pragma unroll
            for (int kx = 0; kx < 3; kx++)
                sum += Wt[c][ky * 3 + kx] * In[sy + ky][sx + kx][c];
        int n = (ty0 + sy) * 64 + (tx0 + sx);
        float val = yb[(size_t)n * EDIM] + sum;
        __nv_bfloat16 h = __float2bfloat16_rn(val);
        __nv_bfloat16 l = __float2bfloat16_rn(val - __bfloat162float(h));
        yhb[(size_t)n * EDIM] = h;
        ylb[(size_t)n * EDIM] = l;
    }
}

// ---------------------------------------------------------------------------
extern "C" void kernel_launch(void* const* d_in, const int* in_sizes, int n_in,
                              void* d_out, int out_size)
{
    const float* x      = (const float*)d_in[0];
    const float* w_q    = (const float*)d_in[1];
    const float* w_kv   = (const float*)d_in[2];
    const float* w_proj = (const float*)d_in[3];
    const float* b_proj = (const float*)d_in[4];
    const float* w_lepe = (const float*)d_in[5];
    const float* b_lepe = (const float*)d_in[6];
    float* out = (float*)d_out;

    float* q = nullptr; float* kv = nullptr;
    cudaGetSymbolAddress((void**)&q,  g_q);
    cudaGetSymbolAddress((void**)&kv, g_kv);
    __nv_bfloat16 *xh, *xl, *yh, *yl, *wqh, *wql, *wkvh, *wkvl, *wph, *wpl;
    cudaGetSymbolAddress((void**)&xh, g_xh);   cudaGetSymbolAddress((void**)&xl, g_xl);
    cudaGetSymbolAddress((void**)&yh, g_yh);   cudaGetSymbolAddress((void**)&yl, g_yl);
    cudaGetSymbolAddress((void**)&wqh, g_wqh); cudaGetSymbolAddress((void**)&wql, g_wql);
    cudaGetSymbolAddress((void**)&wkvh, g_wkvh); cudaGetSymbolAddress((void**)&wkvl, g_wkvl);
    cudaGetSymbolAddress((void**)&wph, g_wph); cudaGetSymbolAddress((void**)&wpl, g_wpl);

    static bool attr_set = false;
    if (!attr_set) {
        cudaFuncSetAttribute(gemm_mma, cudaFuncAttributeMaxDynamicSharedMemorySize, GEMM_DSMEM);
        attr_set = true;
    }

    // 0: operand splits
    split_x_kernel<<<(MTOT * DIMV / 4) / 256, 256>>>(x);
    wsplit_kernel<<<dim3(DIMV / 32, DIMV / 32), 256>>>(w_q, wqh, wql, DIMV, DIMV);
    wsplit_kernel<<<dim3(EDIM / 32, DIMV / 32), 256>>>(w_kv, wkvh, wkvl, DIMV, EDIM);
    wsplit_kernel<<<dim3(DIMV / 32, EDIM / 32), 256>>>(w_proj, wph, wpl, EDIM, DIMV);

    // 1-2: input projections
    gemm_mma<<<dim3(DIMV / 128, MTOT / 128), 256, GEMM_DSMEM>>>(xh, xl, wqh, wql, q, MTOT, DIMV, DIMV, nullptr);
    gemm_mma<<<dim3(EDIM / 128, MTOT / 128), 256, GEMM_DSMEM>>>(xh, xl, wkvh, wkvl, kv, MTOT, EDIM, DIMV, nullptr);

    // 3: softmax over head_dim on k
    softmax_k_kernel<<<(MTOT * HEADS) / 8, 256>>>();

    // 4: K^T V split + reduce
    ktv_part_kernel<<<dim3(BB * HEADS, KTV_SPLIT), 256>>>();
    ktv_reduce_kernel<<<(BB * HEADS * HD * HD) / 256, 256>>>();

    // 5: head-expand ktv
    build_ektv_kernel<<<(BB * 24 * HD * HD) / 256, 256>>>();

    // 6: attn -> y (fp32)
    attn_kernel<<<dim3(NN / 64, 24, BB), 256>>>();

    // 7: LePE conv + add + bf16-split y
    lepe_kernel<<<dim3(16, EDIM / 32, BB), 256>>>(w_lepe, b_lepe);

    // 8: output projection + bias
    gemm_mma<<<dim3(DIMV / 128, MTOT / 128), 256, GEMM_DSMEM>>>(yh, yl, wph, wpl, out, MTOT, DIMV, EDIM, b_proj);
}

// round 6
// speedup vs baseline: 2.3465x; 1.0531x over previous
#include <cuda_runtime.h>
#include <cuda_bf16.h>
#include <cstdint>

// Problem constants
#define BB    8
#define NN    4096
#define DIMV  768
#define HEADS 12
#define HD    64
#define EDIM  1536
#define MTOT  (BB*NN)   // 32768
#define KTV_SPLIT 32

// Scratch (static device allocations)
__device__ float g_q   [(size_t)MTOT * DIMV];
__device__ float g_kv  [(size_t)MTOT * EDIM];   // k cols 0..767 already softmaxed (fused)
__device__ float g_y   [(size_t)MTOT * EDIM];
__device__ float g_ktvp[(size_t)KTV_SPLIT * BB * HEADS * HD * HD];
__device__ float g_ektv[BB * 2*HEADS * HD * HD];

// bf16 hi/lo split operands
__device__ __nv_bfloat16 g_xh[(size_t)MTOT * DIMV];
__device__ __nv_bfloat16 g_xl[(size_t)MTOT * DIMV];
__device__ __nv_bfloat16 g_yh[(size_t)MTOT * EDIM];
__device__ __nv_bfloat16 g_yl[(size_t)MTOT * EDIM];
// weights transposed to [N][K] + split
__device__ __nv_bfloat16 g_wqh [DIMV * DIMV];
__device__ __nv_bfloat16 g_wql [DIMV * DIMV];
__device__ __nv_bfloat16 g_wkvh[EDIM * DIMV];
__device__ __nv_bfloat16 g_wkvl[EDIM * DIMV];
__device__ __nv_bfloat16 g_wph [DIMV * EDIM];
__device__ __nv_bfloat16 g_wpl [DIMV * EDIM];

// ---------------------------------------------------------------------------
// MMA / cp.async helpers
// ---------------------------------------------------------------------------
__device__ __forceinline__ void ldsm_x4(uint32_t r[4], const __nv_bfloat16* p) {
    uint32_t a = (uint32_t)__cvta_generic_to_shared(p);
    asm volatile("ldmatrix.sync.aligned.m8n8.x4.shared.b16 {%0,%1,%2,%3}, [%4];"
                 : "=r"(r[0]), "=r"(r[1]), "=r"(r[2]), "=r"(r[3]) : "r"(a));
}
__device__ __forceinline__ void mma16816(float c[4], const uint32_t a[4],
                                         uint32_t b0, uint32_t b1) {
    asm volatile(
        "mma.sync.aligned.m16n8k16.row.col.f32.bf16.bf16.f32 "
        "{%0,%1,%2,%3}, {%4,%5,%6,%7}, {%8,%9}, {%0,%1,%2,%3};"
        : "+f"(c[0]), "+f"(c[1]), "+f"(c[2]), "+f"(c[3])
        : "r"(a[0]), "r"(a[1]), "r"(a[2]), "r"(a[3]), "r"(b0), "r"(b1));
}
__device__ __forceinline__ void cp_async16(void* smem_dst, const void* gsrc) {
    uint32_t a = (uint32_t)__cvta_generic_to_shared(smem_dst);
    asm volatile("cp.async.cg.shared.global [%0], [%1], 16;" :: "r"(a), "l"(gsrc));
}
#define CP_COMMIT() asm volatile("cp.async.commit_group;" ::: "memory")
#define CP_WAIT0()  asm volatile("cp.async.wait_group 0;" ::: "memory")

#define SPAD   40                      // padded row stride in bf16 (80 B, 16B-mult)
#define PIECE  (128 * SPAD * 2)        // 10240 B  (one 128x32 bf16 tile, padded)
#define STAGE  (4 * PIECE)             // Ah, Al, Bh, Bl
#define GEMM_DSMEM (2 * STAGE)         // 81920 B

// ---------------------------------------------------------------------------
// bf16x3 tensor-core GEMM, pre-split operands, cp.async double-buffered.
// C[M,N] = (Ah+Al)[M,K] @ (Bh+Bl)[N,K]^T (+bias).  128x128 tile, BK=32.
// sm_cols > 0: apply per-row softmax over each aligned 64-col head for
// output cols < sm_cols (head == warpN 64-col span, so register-resident).
// ---------------------------------------------------------------------------
__global__ __launch_bounds__(256, 2) void gemm_mma(
    const __nv_bfloat16* __restrict__ Ah, const __nv_bfloat16* __restrict__ Al,
    const __nv_bfloat16* __restrict__ Bh, const __nv_bfloat16* __restrict__ Bl,
    float* __restrict__ C, int M, int N, int K, const float* __restrict__ bias,
    int sm_cols)
{
    extern __shared__ char smem[];

    const int tid  = threadIdx.x;
    const int lane = tid & 31;
    const int warp = tid >> 5;
    const int warpM = warp >> 1;
    const int warpN = warp & 1;
    const int bm = blockIdx.y * 128;
    const int bn = blockIdx.x * 128;

    float acc[2][8][4];
#pragma unroll
    for (int i = 0; i < 2; i++)
#pragma unroll
        for (int j = 0; j < 8; j++)
#pragma unroll
            for (int l = 0; l < 4; l++) acc[i][j][l] = 0.f;

    const int aRow = warpM * 32 + (lane & 7) + ((lane & 8) ? 8 : 0);
    const int aColOff = (lane & 16) ? 8 : 0;
    const int bRowOff = (lane & 7) + ((lane & 16) ? 8 : 0);
    const int bColOff = (lane & 8) ? 8 : 0;

    const __nv_bfloat16* srcs[4] = {Ah, Al, Bh, Bl};
    const int rowbase[4] = {bm, bm, bn, bn};
    const int row = tid >> 1;
    const int ch0 = (tid & 1) * 2;

    auto issue_stage = [&](int kt) {
        char* st = smem + (kt & 1) * STAGE;
        const int k0 = kt << 5;
#pragma unroll
        for (int p = 0; p < 4; p++) {
            const __nv_bfloat16* src = srcs[p] + (size_t)(rowbase[p] + row) * K + k0;
#pragma unroll
            for (int c = 0; c < 2; c++) {
                int ch = ch0 + c;
                cp_async16(st + p * PIECE + (row * SPAD + ch * 8) * 2, src + ch * 8);
            }
        }
    };

    const int NK = K >> 5;
    issue_stage(0);
    CP_COMMIT();

    for (int kt = 0; kt < NK; kt++) {
        CP_WAIT0();
        __syncthreads();          // also orders buffer reuse for stage kt+1's writes
        if (kt + 1 < NK) issue_stage(kt + 1);
        CP_COMMIT();

        const char* st = smem + (kt & 1) * STAGE;
        const __nv_bfloat16* pAh = (const __nv_bfloat16*)(st);
        const __nv_bfloat16* pAl = (const __nv_bfloat16*)(st + PIECE);
        const __nv_bfloat16* pBh = (const __nv_bfloat16*)(st + 2 * PIECE);
        const __nv_bfloat16* pBl = (const __nv_bfloat16*)(st + 3 * PIECE);

#pragma unroll
        for (int ks = 0; ks < 2; ks++) {
            const int ac = ks * 16 + aColOff;
            const int bc = ks * 16 + bColOff;
            uint32_t ah[2][4], al[2][4];
#pragma unroll
            for (int mi = 0; mi < 2; mi++) {
                ldsm_x4(ah[mi], pAh + (aRow + mi * 16) * SPAD + ac);
                ldsm_x4(al[mi], pAl + (aRow + mi * 16) * SPAD + ac);
            }
#pragma unroll
            for (int n2 = 0; n2 < 4; n2++) {
                const int nr = warpN * 64 + n2 * 16 + bRowOff;
                uint32_t bh[4], bl[4];
                ldsm_x4(bh, pBh + nr * SPAD + bc);
                ldsm_x4(bl, pBl + nr * SPAD + bc);
#pragma unroll
                for (int mi = 0; mi < 2; mi++) {
                    mma16816(acc[mi][2*n2],   ah[mi], bh[0], bh[1]);
                    mma16816(acc[mi][2*n2+1], ah[mi], bh[2], bh[3]);
                    mma16816(acc[mi][2*n2],   ah[mi], bl[0], bl[1]);
                    mma16816(acc[mi][2*n2+1], ah[mi], bl[2], bl[3]);
                    mma16816(acc[mi][2*n2],   al[mi], bh[0], bh[1]);
                    mma16816(acc[mi][2*n2+1], al[mi], bh[2], bh[3]);
                }
            }
        }
        // no end-of-loop sync: next iteration's post-wait sync orders reuse
    }

    // fused softmax over 64-col heads (k region of the kv projection)
    if (sm_cols > 0 && (bn + warpN * 64) < sm_cols) {
#pragma unroll
        for (int mi = 0; mi < 2; mi++) {
#pragma unroll
            for (int hf = 0; hf < 2; hf++) {        // row g (hf=0), row g+8 (hf=1)
                float mx = -3.4e38f;
#pragma unroll
                for (int ni = 0; ni < 8; ni++)
                    mx = fmaxf(mx, fmaxf(acc[mi][ni][2*hf], acc[mi][ni][2*hf+1]));
                mx = fmaxf(mx, __shfl_xor_sync(0xffffffffu, mx, 1));
                mx = fmaxf(mx, __shfl_xor_sync(0xffffffffu, mx, 2));
                float s = 0.f;
#pragma unroll
                for (int ni = 0; ni < 8; ni++) {
                    float e0 = expf(acc[mi][ni][2*hf]     - mx);
                    float e1 = expf(acc[mi][ni][2*hf + 1] - mx);
                    acc[mi][ni][2*hf] = e0; acc[mi][ni][2*hf+1] = e1;
                    s += e0 + e1;
                }
                s += __shfl_xor_sync(0xffffffffu, s, 1);
                s += __shfl_xor_sync(0xffffffffu, s, 2);
                float inv = 1.f / s;
#pragma unroll
                for (int ni = 0; ni < 8; ni++) {
                    acc[mi][ni][2*hf]     *= inv;
                    acc[mi][ni][2*hf + 1] *= inv;
                }
            }
        }
    }

    // epilogue: direct register -> global stores
    const int g = lane >> 2, t = lane & 3;
#pragma unroll
    for (int mi = 0; mi < 2; mi++) {
        int r = bm + warpM * 32 + mi * 16 + g;
#pragma unroll
        for (int ni = 0; ni < 8; ni++) {
            int col = bn + warpN * 64 + ni * 8 + t * 2;
            float b0 = 0.f, b1 = 0.f;
            if (bias) { b0 = bias[col]; b1 = bias[col + 1]; }
            float2 v0 = {acc[mi][ni][0] + b0, acc[mi][ni][1] + b1};
            float2 v1 = {acc[mi][ni][2] + b0, acc[mi][ni][3] + b1};
            *(float2*)(C + (size_t)r * N + col)       = v0;
            *(float2*)(C + (size_t)(r + 8) * N + col) = v1;
        }
    }
}

// ---------------------------------------------------------------------------
// split x (fp32 -> bf16 hi/lo)
// ---------------------------------------------------------------------------
__global__ __launch_bounds__(256) void split_x_kernel(const float* __restrict__ x)
{
    int i = blockIdx.x * 256 + threadIdx.x;
    float4 v = ((const float4*)x)[i];
    float f[4] = {v.x, v.y, v.z, v.w};
    __nv_bfloat162 h01, h23, l01, l23;
    __nv_bfloat16 h, l;
    h = __float2bfloat16_rn(f[0]); l = __float2bfloat16_rn(f[0] - __bfloat162float(h)); h01.x = h; l01.x = l;
    h = __float2bfloat16_rn(f[1]); l = __float2bfloat16_rn(f[1] - __bfloat162float(h)); h01.y = h; l01.y = l;
    h = __float2bfloat16_rn(f[2]); l = __float2bfloat16_rn(f[2] - __bfloat162float(h)); h23.x = h; l23.x = l;
    h = __float2bfloat16_rn(f[3]); l = __float2bfloat16_rn(f[3] - __bfloat162float(h)); h23.y = h; l23.y = l;
    ((__nv_bfloat162*)g_xh)[2 * i] = h01; ((__nv_bfloat162*)g_xh)[2 * i + 1] = h23;
    ((__nv_bfloat162*)g_xl)[2 * i] = l01; ((__nv_bfloat162*)g_xl)[2 * i + 1] = l23;
}

// ---------------------------------------------------------------------------
// weight transpose + split: W[K][N] -> Th/Tl[N][K]
// ---------------------------------------------------------------------------
__global__ __launch_bounds__(256) void wsplit_kernel(
    const float* __restrict__ W, __nv_bfloat16* __restrict__ Th,
    __nv_bfloat16* __restrict__ Tl, int K, int N)
{
    __shared__ float t[32][33];
    int n0 = blockIdx.x * 32, k0 = blockIdx.y * 32;
    int tx = threadIdx.x & 31, ty = threadIdx.x >> 5;
#pragma unroll
    for (int i = 0; i < 4; i++)
        t[ty + i * 8][tx] = W[(size_t)(k0 + ty + i * 8) * N + n0 + tx];
    __syncthreads();
#pragma unroll
    for (int i = 0; i < 4; i++) {
        float f = t[tx][ty + i * 8];
        __nv_bfloat16 h = __float2bfloat16_rn(f);
        __nv_bfloat16 l = __float2bfloat16_rn(f - __bfloat162float(h));
        Th[(size_t)(n0 + ty + i * 8) * K + k0 + tx] = h;
        Tl[(size_t)(n0 + ty + i * 8) * K + k0 + tx] = l;
    }
}

// ---------------------------------------------------------------------------
// ktv partials (k already softmaxed by fused GEMM epilogue)
// ---------------------------------------------------------------------------
__global__ __launch_bounds__(256) void ktv_part_kernel()
{
    int bh = blockIdx.x, s = blockIdx.y;
    int b = bh / HEADS, h = bh % HEADS;
    const int chunk = NN / KTV_SPLIT;            // 128
    const float* ksp = g_kv + (size_t)b * NN * EDIM + h * HD + (size_t)s * chunk * EDIM;
    const float* vp  = ksp + DIMV;

    __shared__ float Ks[32][64];
    __shared__ float Vs[32][64];

    int tid = threadIdx.x;
    int td = tid & 15, te = tid >> 4;
    float acc[4][4];
#pragma unroll
    for (int i = 0; i < 4; i++)
#pragma unroll
        for (int j = 0; j < 4; j++) acc[i][j] = 0.f;

    for (int n0 = 0; n0 < chunk; n0 += 32) {
#pragma unroll
        for (int i = 0; i < 2; i++) {
            int idx4 = tid + i * 256;
            int nl = idx4 >> 4, d4 = (idx4 & 15) * 4;
            *(float4*)&Ks[nl][d4] = *(const float4*)(ksp + (size_t)(n0 + nl) * EDIM + d4);
            *(float4*)&Vs[nl][d4] = *(const float4*)(vp  + (size_t)(n0 + nl) * EDIM + d4);
        }
        __syncthreads();
#pragma unroll 8
        for (int n = 0; n < 32; n++) {
            float a0[4], b0[4];
            *(float4*)a0 = *(const float4*)&Ks[n][td * 4];
            *(float4*)b0 = *(const float4*)&Vs[n][te * 4];
#pragma unroll
            for (int i = 0; i < 4; i++)
#pragma unroll
                for (int j = 0; j < 4; j++)
                    acc[i][j] += a0[i] * b0[j];
        }
        __syncthreads();
    }

    float* out = g_ktvp + ((size_t)s * 96 + bh) * HD * HD;
#pragma unroll
    for (int i = 0; i < 4; i++) {
        float4 v;
        v.x = acc[i][0]; v.y = acc[i][1]; v.z = acc[i][2]; v.w = acc[i][3];
        *(float4*)&out[(td * 4 + i) * HD + te * 4] = v;
    }
}

// reduce partials and scatter straight into both ektv positions (direct + rolled)
__global__ void ktv_reduce_kernel()
{
    int idx = blockIdx.x * 256 + threadIdx.x;    // < 96*4096
    float s = 0.f;
#pragma unroll
    for (int i = 0; i < KTV_SPLIT; i++)
        s += g_ktvp[(size_t)i * 96 * HD * HD + idx];

    int e = idx & 63;
    int d = (idx >> 6) & 63;
    int bh = idx >> 12;
    int h = bh % HEADS, b = bh / HEADS;
    // direct: j = h
    g_ektv[(((size_t)(b * 24 + h) * 64) + d) * 64 + e] = s;
    // rolled: c_t = (h*64 + e - 32) mod 768 -> j = 12 + c_t/64, e2 = c_t%64
    int ct = h * 64 + e - 32;
    if (ct < 0) ct += 768;
    int j2 = 12 + (ct >> 6), e2 = ct & 63;
    g_ektv[(((size_t)(b * 24 + j2) * 64) + d) * 64 + e2] = s;
}

// ---------------------------------------------------------------------------
// attn: y = scale * eq @ ektv  (fp32 out)
// ---------------------------------------------------------------------------
__global__ __launch_bounds__(256) void attn_kernel()
{
    int b = blockIdx.z, j = blockIdx.y, n0 = blockIdx.x * 64;
    __shared__ float Es[64][64];
    __shared__ float Qs[64][64];
    int tid = threadIdx.x;

    const float* ep = g_ektv + (size_t)((b * 24 + j) * 64) * 64;
#pragma unroll
    for (int i = 0; i < 4; i++) {
        int idx4 = tid + i * 256;
        *(float4*)&Es[idx4 >> 4][(idx4 & 15) * 4] = *(const float4*)(ep + idx4 * 4);
    }

    int qbase = (j < 12) ? j * 64 : ((j - 12) * 64 + 32);
    const float* qp = g_q + (size_t)(b * NN + n0) * DIMV;
#pragma unroll
    for (int i = 0; i < 4; i++) {
        int idx4 = tid + i * 256;
        int nl = idx4 >> 4, d4 = (idx4 & 15) * 4;
        int c = qbase + d4;
        if (c >= 768) c -= 768;
        *(float4*)&Qs[nl][d4] = *(const float4*)(qp + (size_t)nl * DIMV + c);
    }
    __syncthreads();

    int r0 = (tid >> 4) * 4, e0 = (tid & 15) * 4;
    float acc[4][4];
#pragma unroll
    for (int i = 0; i < 4; i++)
#pragma unroll
        for (int jj = 0; jj < 4; jj++) acc[i][jj] = 0.f;

#pragma unroll 8
    for (int d = 0; d < 64; d++) {
        float a0[4], b0[4];
        a0[0] = Qs[r0 + 0][d]; a0[1] = Qs[r0 + 1][d];
        a0[2] = Qs[r0 + 2][d]; a0[3] = Qs[r0 + 3][d];
        *(float4*)b0 = *(const float4*)&Es[d][e0];
#pragma unroll
        for (int i = 0; i < 4; i++)
#pragma unroll
            for (int jj = 0; jj < 4; jj++)
                acc[i][jj] += a0[i] * b0[jj];
    }

    const float scale = 0.125f;
#pragma unroll
    for (int i = 0; i < 4; i++) {
        float4 v;
        v.x = scale * acc[i][0]; v.y = scale * acc[i][1];
        v.z = scale * acc[i][2]; v.w = scale * acc[i][3];
        *(float4*)(g_y + (size_t)(b * NN + n0 + r0 + i) * EDIM + j * 64 + e0) = v;
    }
}

// ---------------------------------------------------------------------------
// LePE conv + fuse: (yh,yl) = split(y_attn + conv(q) + bias)
// ---------------------------------------------------------------------------
__global__ __launch_bounds__(256) void lepe_kernel(
    const float* __restrict__ w_lepe, const float* __restrict__ b_lepe)
{
    __shared__ float In[18][18][32];
    __shared__ float Wt[32][9];
    __shared__ float Bsh[32];

    int b = blockIdx.z;
    int chunk = blockIdx.y;
    int tile = blockIdx.x;
    int c0 = chunk * 32;
    int j = c0 >> 6, dlo = c0 & 63;
    int base = (j < 12) ? c0 : ((j - 12) * 64 + 32 + dlo);
    if (base >= 768) base -= 768;
    int ty0 = (tile >> 2) * 16, tx0 = (tile & 3) * 16;
    int tid = threadIdx.x;

    for (int idx = tid; idx < 32 * 9; idx += 256)
        Wt[idx / 9][idx % 9] = w_lepe[c0 * 9 + idx];
    if (tid < 32) Bsh[tid] = b_lepe[c0 + tid];

    const float* qb = g_q + (size_t)b * NN * DIMV + base;
    for (int idx = tid; idx < 18 * 18 * 32; idx += 256) {
        int c = idx & 31;
        int sp = idx >> 5;
        int sy = sp / 18, sx = sp - sy * 18;
        int hh = ty0 + sy - 1, ww = tx0 + sx - 1;
        float v = 0.f;
        if (hh >= 0 && hh < 64 && ww >= 0 && ww < 64)
            v = qb[(size_t)(hh * 64 + ww) * DIMV + c];
        In[sy][sx][c] = v;
    }
    __syncthreads();

    int c = tid & 31, sg = tid >> 5;
    const float* yb = g_y + (size_t)b * NN * EDIM + c0 + c;
    __nv_bfloat16* yhb = g_yh + (size_t)b * NN * EDIM + c0 + c;
    __nv_bfloat16* ylb = g_yl + (size_t)b * NN * EDIM + c0 + c;
#pragma unroll 4
    for (int s = 0; s < 32; s++) {
        int sp = sg * 32 + s;
        int sy = sp >> 4, sx = sp & 15;
        float sum = Bsh[c];
#pragma unroll
        for (int ky = 0; ky < 3; ky++)
#pragma unroll
            for (int kx = 0; kx < 3; kx++)
                sum += Wt[c][ky * 3 + kx] * In[sy + ky][sx + kx][c];
        int n = (ty0 + sy) * 64 + (tx0 + sx);
        float val = yb[(size_t)n * EDIM] + sum;
        __nv_bfloat16 h = __float2bfloat16_rn(val);
        __nv_bfloat16 l = __float2bfloat16_rn(val - __bfloat162float(h));
        yhb[(size_t)n * EDIM] = h;
        ylb[(size_t)n * EDIM] = l;
    }
}

// ---------------------------------------------------------------------------
extern "C" void kernel_launch(void* const* d_in, const int* in_sizes, int n_in,
                              void* d_out, int out_size)
{
    const float* x      = (const float*)d_in[0];
    const float* w_q    = (const float*)d_in[1];
    const float* w_kv   = (const float*)d_in[2];
    const float* w_proj = (const float*)d_in[3];
    const float* b_proj = (const float*)d_in[4];
    const float* w_lepe = (const float*)d_in[5];
    const float* b_lepe = (const float*)d_in[6];
    float* out = (float*)d_out;

    float* q = nullptr; float* kv = nullptr;
    cudaGetSymbolAddress((void**)&q,  g_q);
    cudaGetSymbolAddress((void**)&kv, g_kv);
    __nv_bfloat16 *xh, *xl, *yh, *yl, *wqh, *wql, *wkvh, *wkvl, *wph, *wpl;
    cudaGetSymbolAddress((void**)&xh, g_xh);   cudaGetSymbolAddress((void**)&xl, g_xl);
    cudaGetSymbolAddress((void**)&yh, g_yh);   cudaGetSymbolAddress((void**)&yl, g_yl);
    cudaGetSymbolAddress((void**)&wqh, g_wqh); cudaGetSymbolAddress((void**)&wql, g_wql);
    cudaGetSymbolAddress((void**)&wkvh, g_wkvh); cudaGetSymbolAddress((void**)&wkvl, g_wkvl);
    cudaGetSymbolAddress((void**)&wph, g_wph); cudaGetSymbolAddress((void**)&wpl, g_wpl);

    static bool attr_set = false;
    if (!attr_set) {
        cudaFuncSetAttribute(gemm_mma, cudaFuncAttributeMaxDynamicSharedMemorySize, GEMM_DSMEM);
        attr_set = true;
    }

    // 0: operand splits
    split_x_kernel<<<(MTOT * DIMV / 4) / 256, 256>>>(x);
    wsplit_kernel<<<dim3(DIMV / 32, DIMV / 32), 256>>>(w_q, wqh, wql, DIMV, DIMV);
    wsplit_kernel<<<dim3(EDIM / 32, DIMV / 32), 256>>>(w_kv, wkvh, wkvl, DIMV, EDIM);
    wsplit_kernel<<<dim3(DIMV / 32, EDIM / 32), 256>>>(w_proj, wph, wpl, EDIM, DIMV);

    // 1: q projection
    gemm_mma<<<dim3(DIMV / 128, MTOT / 128), 256, GEMM_DSMEM>>>(
        xh, xl, wqh, wql, q, MTOT, DIMV, DIMV, nullptr, 0);
    // 2: kv projection with fused k-softmax (cols < 768)
    gemm_mma<<<dim3(EDIM / 128, MTOT / 128), 256, GEMM_DSMEM>>>(
        xh, xl, wkvh, wkvl, kv, MTOT, EDIM, DIMV, nullptr, DIMV);

    // 3: K^T V split + reduce (reduce scatters into ektv directly)
    ktv_part_kernel<<<dim3(BB * HEADS, KTV_SPLIT), 256>>>();
    ktv_reduce_kernel<<<(BB * HEADS * HD * HD) / 256, 256>>>();

    // 4: attn -> y (fp32)
    attn_kernel<<<dim3(NN / 64, 24, BB), 256>>>();

    // 5: LePE conv + add + bf16-split y
    lepe_kernel<<<dim3(16, EDIM / 32, BB), 256>>>(w_lepe, b_lepe);

    // 6: output projection + bias
    gemm_mma<<<dim3(DIMV / 128, MTOT / 128), 256, GEMM_DSMEM>>>(
        yh, yl, wph, wpl, out, MTOT, DIMV, EDIM, b_proj, 0);
}

// round 7
// speedup vs baseline: 2.4679x; 1.0517x over previous
#include <cuda_runtime.h>
#include <cuda_bf16.h>
#include <cstdint>

// Problem constants
#define BB    8
#define NN    4096
#define DIMV  768
#define HEADS 12
#define HD    64
#define EDIM  1536
#define MTOT  (BB*NN)   // 32768
#define KTV_SPLIT 32

// Scratch (static device allocations)
__device__ float g_q   [(size_t)MTOT * DIMV];
__device__ float g_kv  [(size_t)MTOT * EDIM];   // k cols 0..767 already softmaxed (fused)
__device__ float g_ktvp[(size_t)KTV_SPLIT * BB * HEADS * HD * HD];
__device__ float g_ektv[BB * 2*HEADS * HD * HD];

// bf16 hi/lo split operands
__device__ __nv_bfloat16 g_xh[(size_t)MTOT * DIMV];
__device__ __nv_bfloat16 g_xl[(size_t)MTOT * DIMV];
__device__ __nv_bfloat16 g_yh[(size_t)MTOT * EDIM];
__device__ __nv_bfloat16 g_yl[(size_t)MTOT * EDIM];
// weights transposed to [N][K] + split
__device__ __nv_bfloat16 g_wqh [DIMV * DIMV];
__device__ __nv_bfloat16 g_wql [DIMV * DIMV];
__device__ __nv_bfloat16 g_wkvh[EDIM * DIMV];
__device__ __nv_bfloat16 g_wkvl[EDIM * DIMV];
__device__ __nv_bfloat16 g_wph [DIMV * EDIM];
__device__ __nv_bfloat16 g_wpl [DIMV * EDIM];

// ---------------------------------------------------------------------------
// MMA / cp.async helpers
// ---------------------------------------------------------------------------
__device__ __forceinline__ void ldsm_x4(uint32_t r[4], const __nv_bfloat16* p) {
    uint32_t a = (uint32_t)__cvta_generic_to_shared(p);
    asm volatile("ldmatrix.sync.aligned.m8n8.x4.shared.b16 {%0,%1,%2,%3}, [%4];"
                 : "=r"(r[0]), "=r"(r[1]), "=r"(r[2]), "=r"(r[3]) : "r"(a));
}
__device__ __forceinline__ void mma16816(float c[4], const uint32_t a[4],
                                         uint32_t b0, uint32_t b1) {
    asm volatile(
        "mma.sync.aligned.m16n8k16.row.col.f32.bf16.bf16.f32 "
        "{%0,%1,%2,%3}, {%4,%5,%6,%7}, {%8,%9}, {%0,%1,%2,%3};"
        : "+f"(c[0]), "+f"(c[1]), "+f"(c[2]), "+f"(c[3])
        : "r"(a[0]), "r"(a[1]), "r"(a[2]), "r"(a[3]), "r"(b0), "r"(b1));
}
__device__ __forceinline__ void cp_async16(void* smem_dst, const void* gsrc) {
    uint32_t a = (uint32_t)__cvta_generic_to_shared(smem_dst);
    asm volatile("cp.async.cg.shared.global [%0], [%1], 16;" :: "r"(a), "l"(gsrc));
}
#define CP_COMMIT() asm volatile("cp.async.commit_group;" ::: "memory")
#define CP_WAIT0()  asm volatile("cp.async.wait_group 0;" ::: "memory")

#define SPAD   40                      // padded row stride in bf16 (80 B, 16B-mult)
#define PIECE  (128 * SPAD * 2)        // 10240 B  (one 128x32 bf16 tile, padded)
#define STAGE  (4 * PIECE)             // Ah, Al, Bh, Bl
#define GEMM_DSMEM (2 * STAGE)         // 81920 B

// ---------------------------------------------------------------------------
// bf16x3 tensor-core GEMM, pre-split operands, cp.async double-buffered.
// C[M,N] = (Ah+Al)[M,K] @ (Bh+Bl)[N,K]^T (+bias).  128x128 tile, BK=32.
// sm_cols > 0: per-row softmax over each aligned 64-col head for cols < sm_cols.
// ---------------------------------------------------------------------------
__global__ __launch_bounds__(256, 2) void gemm_mma(
    const __nv_bfloat16* __restrict__ Ah, const __nv_bfloat16* __restrict__ Al,
    const __nv_bfloat16* __restrict__ Bh, const __nv_bfloat16* __restrict__ Bl,
    float* __restrict__ C, int M, int N, int K, const float* __restrict__ bias,
    int sm_cols)
{
    extern __shared__ char smem[];

    const int tid  = threadIdx.x;
    const int lane = tid & 31;
    const int warp = tid >> 5;
    const int warpM = warp >> 1;
    const int warpN = warp & 1;
    const int bm = blockIdx.y * 128;
    const int bn = blockIdx.x * 128;

    float acc[2][8][4];
#pragma unroll
    for (int i = 0; i < 2; i++)
#pragma unroll
        for (int j = 0; j < 8; j++)
#pragma unroll
            for (int l = 0; l < 4; l++) acc[i][j][l] = 0.f;

    const int aRow = warpM * 32 + (lane & 7) + ((lane & 8) ? 8 : 0);
    const int aColOff = (lane & 16) ? 8 : 0;
    const int bRowOff = (lane & 7) + ((lane & 16) ? 8 : 0);
    const int bColOff = (lane & 8) ? 8 : 0;

    const __nv_bfloat16* srcs[4] = {Ah, Al, Bh, Bl};
    const int rowbase[4] = {bm, bm, bn, bn};
    const int row = tid >> 1;
    const int ch0 = (tid & 1) * 2;

    auto issue_stage = [&](int kt) {
        char* st = smem + (kt & 1) * STAGE;
        const int k0 = kt << 5;
#pragma unroll
        for (int p = 0; p < 4; p++) {
            const __nv_bfloat16* src = srcs[p] + (size_t)(rowbase[p] + row) * K + k0;
#pragma unroll
            for (int c = 0; c < 2; c++) {
                int ch = ch0 + c;
                cp_async16(st + p * PIECE + (row * SPAD + ch * 8) * 2, src + ch * 8);
            }
        }
    };

    const int NK = K >> 5;
    issue_stage(0);
    CP_COMMIT();

    for (int kt = 0; kt < NK; kt++) {
        CP_WAIT0();
        __syncthreads();
        if (kt + 1 < NK) issue_stage(kt + 1);
        CP_COMMIT();

        const char* st = smem + (kt & 1) * STAGE;
        const __nv_bfloat16* pAh = (const __nv_bfloat16*)(st);
        const __nv_bfloat16* pAl = (const __nv_bfloat16*)(st + PIECE);
        const __nv_bfloat16* pBh = (const __nv_bfloat16*)(st + 2 * PIECE);
        const __nv_bfloat16* pBl = (const __nv_bfloat16*)(st + 3 * PIECE);

#pragma unroll
        for (int ks = 0; ks < 2; ks++) {
            const int ac = ks * 16 + aColOff;
            const int bc = ks * 16 + bColOff;
            uint32_t ah[2][4], al[2][4];
#pragma unroll
            for (int mi = 0; mi < 2; mi++) {
                ldsm_x4(ah[mi], pAh + (aRow + mi * 16) * SPAD + ac);
                ldsm_x4(al[mi], pAl + (aRow + mi * 16) * SPAD + ac);
            }
#pragma unroll
            for (int n2 = 0; n2 < 4; n2++) {
                const int nr = warpN * 64 + n2 * 16 + bRowOff;
                uint32_t bh[4], bl[4];
                ldsm_x4(bh, pBh + nr * SPAD + bc);
                ldsm_x4(bl, pBl + nr * SPAD + bc);
#pragma unroll
                for (int mi = 0; mi < 2; mi++) {
                    mma16816(acc[mi][2*n2],   ah[mi], bh[0], bh[1]);
                    mma16816(acc[mi][2*n2+1], ah[mi], bh[2], bh[3]);
                    mma16816(acc[mi][2*n2],   ah[mi], bl[0], bl[1]);
                    mma16816(acc[mi][2*n2+1], ah[mi], bl[2], bl[3]);
                    mma16816(acc[mi][2*n2],   al[mi], bh[0], bh[1]);
                    mma16816(acc[mi][2*n2+1], al[mi], bh[2], bh[3]);
                }
            }
        }
    }

    // fused softmax over 64-col heads (k region of the kv projection)
    if (sm_cols > 0 && (bn + warpN * 64) < sm_cols) {
#pragma unroll
        for (int mi = 0; mi < 2; mi++) {
#pragma unroll
            for (int hf = 0; hf < 2; hf++) {
                float mx = -3.4e38f;
#pragma unroll
                for (int ni = 0; ni < 8; ni++)
                    mx = fmaxf(mx, fmaxf(acc[mi][ni][2*hf], acc[mi][ni][2*hf+1]));
                mx = fmaxf(mx, __shfl_xor_sync(0xffffffffu, mx, 1));
                mx = fmaxf(mx, __shfl_xor_sync(0xffffffffu, mx, 2));
                float s = 0.f;
#pragma unroll
                for (int ni = 0; ni < 8; ni++) {
                    float e0 = expf(acc[mi][ni][2*hf]     - mx);
                    float e1 = expf(acc[mi][ni][2*hf + 1] - mx);
                    acc[mi][ni][2*hf] = e0; acc[mi][ni][2*hf+1] = e1;
                    s += e0 + e1;
                }
                s += __shfl_xor_sync(0xffffffffu, s, 1);
                s += __shfl_xor_sync(0xffffffffu, s, 2);
                float inv = 1.f / s;
#pragma unroll
                for (int ni = 0; ni < 8; ni++) {
                    acc[mi][ni][2*hf]     *= inv;
                    acc[mi][ni][2*hf + 1] *= inv;
                }
            }
        }
    }

    const int g = lane >> 2, t = lane & 3;
#pragma unroll
    for (int mi = 0; mi < 2; mi++) {
        int r = bm + warpM * 32 + mi * 16 + g;
#pragma unroll
        for (int ni = 0; ni < 8; ni++) {
            int col = bn + warpN * 64 + ni * 8 + t * 2;
            float b0 = 0.f, b1 = 0.f;
            if (bias) { b0 = bias[col]; b1 = bias[col + 1]; }
            float2 v0 = {acc[mi][ni][0] + b0, acc[mi][ni][1] + b1};
            float2 v1 = {acc[mi][ni][2] + b0, acc[mi][ni][3] + b1};
            *(float2*)(C + (size_t)r * N + col)       = v0;
            *(float2*)(C + (size_t)(r + 8) * N + col) = v1;
        }
    }
}

// ---------------------------------------------------------------------------
// split x (fp32 -> bf16 hi/lo)
// ---------------------------------------------------------------------------
__global__ __launch_bounds__(256) void split_x_kernel(const float* __restrict__ x)
{
    int i = blockIdx.x * 256 + threadIdx.x;
    float4 v = ((const float4*)x)[i];
    float f[4] = {v.x, v.y, v.z, v.w};
    __nv_bfloat162 h01, h23, l01, l23;
    __nv_bfloat16 h, l;
    h = __float2bfloat16_rn(f[0]); l = __float2bfloat16_rn(f[0] - __bfloat162float(h)); h01.x = h; l01.x = l;
    h = __float2bfloat16_rn(f[1]); l = __float2bfloat16_rn(f[1] - __bfloat162float(h)); h01.y = h; l01.y = l;
    h = __float2bfloat16_rn(f[2]); l = __float2bfloat16_rn(f[2] - __bfloat162float(h)); h23.x = h; l23.x = l;
    h = __float2bfloat16_rn(f[3]); l = __float2bfloat16_rn(f[3] - __bfloat162float(h)); h23.y = h; l23.y = l;
    ((__nv_bfloat162*)g_xh)[2 * i] = h01; ((__nv_bfloat162*)g_xh)[2 * i + 1] = h23;
    ((__nv_bfloat162*)g_xl)[2 * i] = l01; ((__nv_bfloat162*)g_xl)[2 * i + 1] = l23;
}

// ---------------------------------------------------------------------------
// weight transpose + split: W[K][N] -> Th/Tl[N][K]
// ---------------------------------------------------------------------------
__global__ __launch_bounds__(256) void wsplit_kernel(
    const float* __restrict__ W, __nv_bfloat16* __restrict__ Th,
    __nv_bfloat16* __restrict__ Tl, int K, int N)
{
    __shared__ float t[32][33];
    int n0 = blockIdx.x * 32, k0 = blockIdx.y * 32;
    int tx = threadIdx.x & 31, ty = threadIdx.x >> 5;
#pragma unroll
    for (int i = 0; i < 4; i++)
        t[ty + i * 8][tx] = W[(size_t)(k0 + ty + i * 8) * N + n0 + tx];
    __syncthreads();
#pragma unroll
    for (int i = 0; i < 4; i++) {
        float f = t[tx][ty + i * 8];
        __nv_bfloat16 h = __float2bfloat16_rn(f);
        __nv_bfloat16 l = __float2bfloat16_rn(f - __bfloat162float(h));
        Th[(size_t)(n0 + ty + i * 8) * K + k0 + tx] = h;
        Tl[(size_t)(n0 + ty + i * 8) * K + k0 + tx] = l;
    }
}

// ---------------------------------------------------------------------------
// ktv partials (k already softmaxed by fused GEMM epilogue)
// ---------------------------------------------------------------------------
__global__ __launch_bounds__(256) void ktv_part_kernel()
{
    int bh = blockIdx.x, s = blockIdx.y;
    int b = bh / HEADS, h = bh % HEADS;
    const int chunk = NN / KTV_SPLIT;            // 128
    const float* ksp = g_kv + (size_t)b * NN * EDIM + h * HD + (size_t)s * chunk * EDIM;
    const float* vp  = ksp + DIMV;

    __shared__ float Ks[32][64];
    __shared__ float Vs[32][64];

    int tid = threadIdx.x;
    int td = tid & 15, te = tid >> 4;
    float acc[4][4];
#pragma unroll
    for (int i = 0; i < 4; i++)
#pragma unroll
        for (int j = 0; j < 4; j++) acc[i][j] = 0.f;

    for (int n0 = 0; n0 < chunk; n0 += 32) {
#pragma unroll
        for (int i = 0; i < 2; i++) {
            int idx4 = tid + i * 256;
            int nl = idx4 >> 4, d4 = (idx4 & 15) * 4;
            *(float4*)&Ks[nl][d4] = *(const float4*)(ksp + (size_t)(n0 + nl) * EDIM + d4);
            *(float4*)&Vs[nl][d4] = *(const float4*)(vp  + (size_t)(n0 + nl) * EDIM + d4);
        }
        __syncthreads();
#pragma unroll 8
        for (int n = 0; n < 32; n++) {
            float a0[4], b0[4];
            *(float4*)a0 = *(const float4*)&Ks[n][td * 4];
            *(float4*)b0 = *(const float4*)&Vs[n][te * 4];
#pragma unroll
            for (int i = 0; i < 4; i++)
#pragma unroll
                for (int j = 0; j < 4; j++)
                    acc[i][j] += a0[i] * b0[j];
        }
        __syncthreads();
    }

    float* out = g_ktvp + ((size_t)s * 96 + bh) * HD * HD;
#pragma unroll
    for (int i = 0; i < 4; i++) {
        float4 v;
        v.x = acc[i][0]; v.y = acc[i][1]; v.z = acc[i][2]; v.w = acc[i][3];
        *(float4*)&out[(td * 4 + i) * HD + te * 4] = v;
    }
}

// reduce partials and scatter straight into both ektv positions (direct + rolled)
__global__ void ktv_reduce_kernel()
{
    int idx = blockIdx.x * 256 + threadIdx.x;    // < 96*4096
    float s = 0.f;
#pragma unroll
    for (int i = 0; i < KTV_SPLIT; i++)
        s += g_ktvp[(size_t)i * 96 * HD * HD + idx];

    int e = idx & 63;
    int d = (idx >> 6) & 63;
    int bh = idx >> 12;
    int h = bh % HEADS, b = bh / HEADS;
    g_ektv[(((size_t)(b * 24 + h) * 64) + d) * 64 + e] = s;
    int ct = h * 64 + e - 32;
    if (ct < 0) ct += 768;
    int j2 = 12 + (ct >> 6), e2 = ct & 63;
    g_ektv[(((size_t)(b * 24 + j2) * 64) + d) * 64 + e2] = s;
}

// ---------------------------------------------------------------------------
// Fused attn + LePE: block (y0, j, b) covers image row y0 (64 pixels) x 64
// expanded channels. Loads 3 q row-slabs (y0-1..y0+1) of the j-mapped 64
// q-columns; attn from center slab vs ektv; depthwise 3x3 conv from all 3;
// writes bf16 hi/lo split of (0.125*attn + conv + b_lepe) directly.
// ---------------------------------------------------------------------------
#define QS_STRIDE 72
#define AL_ES   0
#define AL_QS   16384
#define AL_WT   (AL_QS + 3*64*QS_STRIDE*4)   // 16384 + 55296 = 71680
#define AL_BS   (AL_WT + 64*9*4)             // 73984
#define AL_SMEM (AL_BS + 256)                // 74240

__global__ __launch_bounds__(256) void attn_lepe_kernel(
    const float* __restrict__ w_lepe, const float* __restrict__ b_lepe)
{
    extern __shared__ char sm[];
    float* Es = (float*)(sm + AL_ES);        // [64][64]
    float* Qs = (float*)(sm + AL_QS);        // [3][64][QS_STRIDE]
    float* Wt = (float*)(sm + AL_WT);        // [64][9]
    float* Bs = (float*)(sm + AL_BS);        // [64]

    const int y0 = blockIdx.x, j = blockIdx.y, b = blockIdx.z;
    const int tid = threadIdx.x;

    const float* ep = g_ektv + (size_t)((b * 24 + j) * 64) * 64;
#pragma unroll
    for (int i = 0; i < 4; i++) {
        int idx4 = tid + i * 256;
        *(float4*)&Es[idx4 * 4] = *(const float4*)(ep + idx4 * 4);
    }
    for (int idx = tid; idx < 64 * 9; idx += 256) Wt[idx] = w_lepe[(j * 64) * 9 + idx];
    if (tid < 64) Bs[tid] = b_lepe[j * 64 + tid];

    const int qbase = (j < 12) ? j * 64 : ((j - 12) * 64 + 32);
#pragma unroll
    for (int s = 0; s < 3; s++) {
        int y = y0 + s - 1;
        bool valid = (y >= 0) && (y < 64);
        const float* qrow = g_q + ((size_t)(b * NN) + y * 64) * DIMV;
#pragma unroll
        for (int i = 0; i < 4; i++) {
            int idx4 = tid + i * 256;              // 0..1023
            int x = idx4 >> 4, d4 = (idx4 & 15) * 4;
            float4 v = make_float4(0.f, 0.f, 0.f, 0.f);
            if (valid) {
                int c = qbase + d4;
                if (c >= 768) c -= 768;
                v = *(const float4*)(qrow + (size_t)x * DIMV + c);
            }
            *(float4*)&Qs[(s * 64 + x) * QS_STRIDE + d4] = v;
        }
    }
    __syncthreads();

    const int r0 = (tid >> 4) * 4, e0 = (tid & 15) * 4;
    float acc[4][4];
#pragma unroll
    for (int i = 0; i < 4; i++)
#pragma unroll
        for (int jj = 0; jj < 4; jj++) acc[i][jj] = 0.f;

    const float* Qc = Qs + 64 * QS_STRIDE;       // center slab (s=1)
#pragma unroll 8
    for (int d = 0; d < 64; d++) {
        float a0[4], b0[4];
        a0[0] = Qc[(r0 + 0) * QS_STRIDE + d];
        a0[1] = Qc[(r0 + 1) * QS_STRIDE + d];
        a0[2] = Qc[(r0 + 2) * QS_STRIDE + d];
        a0[3] = Qc[(r0 + 3) * QS_STRIDE + d];
        *(float4*)b0 = *(const float4*)&Es[d * 64 + e0];
#pragma unroll
        for (int i = 0; i < 4; i++)
#pragma unroll
            for (int jj = 0; jj < 4; jj++)
                acc[i][jj] += a0[i] * b0[jj];
    }

    const int n0 = y0 * 64;
#pragma unroll
    for (int i = 0; i < 4; i++) {
        const int x = r0 + i;
        uint32_t hp[2], lp[2];
        float vh[4], vl[4];
#pragma unroll
        for (int jj = 0; jj < 4; jj++) {
            const int e = e0 + jj;
            float sum = Bs[e];
#pragma unroll
            for (int ky = 0; ky < 3; ky++) {
#pragma unroll
                for (int kx = 0; kx < 3; kx++) {
                    int xx = x + kx - 1;
                    float qv = (xx >= 0 && xx < 64) ? Qs[(ky * 64 + xx) * QS_STRIDE + e] : 0.f;
                    sum += Wt[e * 9 + ky * 3 + kx] * qv;
                }
            }
            float val = 0.125f * acc[i][jj] + sum;
            __nv_bfloat16 h = __float2bfloat16_rn(val);
            __nv_bfloat16 l = __float2bfloat16_rn(val - __bfloat162float(h));
            vh[jj] = __bfloat162float(h);   // keep exact bf16 values
            ((__nv_bfloat16*)hp)[jj] = h;
            ((__nv_bfloat16*)lp)[jj] = l;
            (void)vl;
        }
        size_t off = ((size_t)(b * NN) + n0 + x) * EDIM + j * 64 + e0;
        *(uint2*)(g_yh + off) = make_uint2(hp[0], hp[1]);
        *(uint2*)(g_yl + off) = make_uint2(lp[0], lp[1]);
    }
}

// ---------------------------------------------------------------------------
extern "C" void kernel_launch(void* const* d_in, const int* in_sizes, int n_in,
                              void* d_out, int out_size)
{
    const float* x      = (const float*)d_in[0];
    const float* w_q    = (const float*)d_in[1];
    const float* w_kv   = (const float*)d_in[2];
    const float* w_proj = (const float*)d_in[3];
    const float* b_proj = (const float*)d_in[4];
    const float* w_lepe = (const float*)d_in[5];
    const float* b_lepe = (const float*)d_in[6];
    float* out = (float*)d_out;

    float* q = nullptr; float* kv = nullptr;
    cudaGetSymbolAddress((void**)&q,  g_q);
    cudaGetSymbolAddress((void**)&kv, g_kv);
    __nv_bfloat16 *xh, *xl, *yh, *yl, *wqh, *wql, *wkvh, *wkvl, *wph, *wpl;
    cudaGetSymbolAddress((void**)&xh, g_xh);   cudaGetSymbolAddress((void**)&xl, g_xl);
    cudaGetSymbolAddress((void**)&yh, g_yh);   cudaGetSymbolAddress((void**)&yl, g_yl);
    cudaGetSymbolAddress((void**)&wqh, g_wqh); cudaGetSymbolAddress((void**)&wql, g_wql);
    cudaGetSymbolAddress((void**)&wkvh, g_wkvh); cudaGetSymbolAddress((void**)&wkvl, g_wkvl);
    cudaGetSymbolAddress((void**)&wph, g_wph); cudaGetSymbolAddress((void**)&wpl, g_wpl);

    static bool attr_set = false;
    if (!attr_set) {
        cudaFuncSetAttribute(gemm_mma, cudaFuncAttributeMaxDynamicSharedMemorySize, GEMM_DSMEM);
        cudaFuncSetAttribute(attn_lepe_kernel, cudaFuncAttributeMaxDynamicSharedMemorySize, AL_SMEM);
        attr_set = true;
    }

    // 0: operand splits
    split_x_kernel<<<(MTOT * DIMV / 4) / 256, 256>>>(x);
    wsplit_kernel<<<dim3(DIMV / 32, DIMV / 32), 256>>>(w_q, wqh, wql, DIMV, DIMV);
    wsplit_kernel<<<dim3(EDIM / 32, DIMV / 32), 256>>>(w_kv, wkvh, wkvl, DIMV, EDIM);
    wsplit_kernel<<<dim3(DIMV / 32, EDIM / 32), 256>>>(w_proj, wph, wpl, EDIM, DIMV);

    // 1: q projection
    gemm_mma<<<dim3(DIMV / 128, MTOT / 128), 256, GEMM_DSMEM>>>(
        xh, xl, wqh, wql, q, MTOT, DIMV, DIMV, nullptr, 0);
    // 2: kv projection with fused k-softmax
    gemm_mma<<<dim3(EDIM / 128, MTOT / 128), 256, GEMM_DSMEM>>>(
        xh, xl, wkvh, wkvl, kv, MTOT, EDIM, DIMV, nullptr, DIMV);

    // 3: K^T V split + reduce (reduce scatters into ektv directly)
    ktv_part_kernel<<<dim3(BB * HEADS, KTV_SPLIT), 256>>>();
    ktv_reduce_kernel<<<(BB * HEADS * HD * HD) / 256, 256>>>();

    // 4: fused attn + LePE -> yh/yl (bf16 split)
    attn_lepe_kernel<<<dim3(64, 24, BB), 256, AL_SMEM>>>(w_lepe, b_lepe);

    // 5: output projection + bias
    gemm_mma<<<dim3(DIMV / 128, MTOT / 128), 256, GEMM_DSMEM>>>(
        yh, yl, wph, wpl, out, MTOT, DIMV, EDIM, b_proj, 0);
}

// round 8
// speedup vs baseline: 2.5365x; 1.0278x over previous
#include <cuda_runtime.h>
#include <cuda_bf16.h>
#include <cstdint>

// Problem constants
#define BB    8
#define NN    4096
#define DIMV  768
#define HEADS 12
#define HD    64
#define EDIM  1536
#define MTOT  (BB*NN)   // 32768
#define KTV_SPLIT 32
#define NQKV  2304      // merged q|kv output width

// Scratch (static device allocations)
__device__ float g_q   [(size_t)MTOT * DIMV];
__device__ float g_kv  [(size_t)MTOT * EDIM];   // k cols 0..767 softmaxed (fused)
__device__ float g_ktvp[(size_t)KTV_SPLIT * BB * HEADS * HD * HD];
__device__ float g_ektv[BB * 2*HEADS * HD * HD];

// bf16 hi/lo split operands
__device__ __nv_bfloat16 g_xh[(size_t)MTOT * DIMV];
__device__ __nv_bfloat16 g_xl[(size_t)MTOT * DIMV];
__device__ __nv_bfloat16 g_yh[(size_t)MTOT * EDIM];
__device__ __nv_bfloat16 g_yl[(size_t)MTOT * EDIM];
// weights transposed to [N][K] + split; q|kv merged
__device__ __nv_bfloat16 g_wqkvh[NQKV * DIMV];
__device__ __nv_bfloat16 g_wqkvl[NQKV * DIMV];
__device__ __nv_bfloat16 g_wph  [DIMV * EDIM];
__device__ __nv_bfloat16 g_wpl  [DIMV * EDIM];

// ---------------------------------------------------------------------------
// MMA / cp.async helpers
// ---------------------------------------------------------------------------
__device__ __forceinline__ void ldsm_x4(uint32_t r[4], const __nv_bfloat16* p) {
    uint32_t a = (uint32_t)__cvta_generic_to_shared(p);
    asm volatile("ldmatrix.sync.aligned.m8n8.x4.shared.b16 {%0,%1,%2,%3}, [%4];"
                 : "=r"(r[0]), "=r"(r[1]), "=r"(r[2]), "=r"(r[3]) : "r"(a));
}
__device__ __forceinline__ void mma16816(float c[4], const uint32_t a[4],
                                         uint32_t b0, uint32_t b1) {
    asm volatile(
        "mma.sync.aligned.m16n8k16.row.col.f32.bf16.bf16.f32 "
        "{%0,%1,%2,%3}, {%4,%5,%6,%7}, {%8,%9}, {%0,%1,%2,%3};"
        : "+f"(c[0]), "+f"(c[1]), "+f"(c[2]), "+f"(c[3])
        : "r"(a[0]), "r"(a[1]), "r"(a[2]), "r"(a[3]), "r"(b0), "r"(b1));
}
__device__ __forceinline__ void cp_async16(void* smem_dst, const void* gsrc) {
    uint32_t a = (uint32_t)__cvta_generic_to_shared(smem_dst);
    asm volatile("cp.async.cg.shared.global [%0], [%1], 16;" :: "r"(a), "l"(gsrc));
}
#define CP_COMMIT() asm volatile("cp.async.commit_group;" ::: "memory")
#define CP_WAIT0()  asm volatile("cp.async.wait_group 0;" ::: "memory")

#define SPAD   40
#define PIECE  (128 * SPAD * 2)        // 10240 B
#define STAGE  (4 * PIECE)
#define GEMM_DSMEM (2 * STAGE)         // 81920 B

// ---------------------------------------------------------------------------
// bf16x3 tensor-core GEMM, pre-split operands, cp.async double-buffered.
// C routed by column: col < csplit -> C1 (ld1), else C2 (ld2, col-csplit).
// Softmax over 64-col heads applied for cols in [sm_lo, sm_hi).
// ---------------------------------------------------------------------------
__global__ __launch_bounds__(256, 2) void gemm_mma(
    const __nv_bfloat16* __restrict__ Ah, const __nv_bfloat16* __restrict__ Al,
    const __nv_bfloat16* __restrict__ Bh, const __nv_bfloat16* __restrict__ Bl,
    float* __restrict__ C1, float* __restrict__ C2, int csplit, int ld1, int ld2,
    int M, int N, int K, const float* __restrict__ bias, int sm_lo, int sm_hi)
{
    extern __shared__ char smem[];

    const int tid  = threadIdx.x;
    const int lane = tid & 31;
    const int warp = tid >> 5;
    const int warpM = warp >> 1;
    const int warpN = warp & 1;
    const int bm = blockIdx.y * 128;
    const int bn = blockIdx.x * 128;

    float acc[2][8][4];
#pragma unroll
    for (int i = 0; i < 2; i++)
#pragma unroll
        for (int j = 0; j < 8; j++)
#pragma unroll
            for (int l = 0; l < 4; l++) acc[i][j][l] = 0.f;

    const int aRow = warpM * 32 + (lane & 7) + ((lane & 8) ? 8 : 0);
    const int aColOff = (lane & 16) ? 8 : 0;
    const int bRowOff = (lane & 7) + ((lane & 16) ? 8 : 0);
    const int bColOff = (lane & 8) ? 8 : 0;

    const __nv_bfloat16* srcs[4] = {Ah, Al, Bh, Bl};
    const int rowbase[4] = {bm, bm, bn, bn};
    const int row = tid >> 1;
    const int ch0 = (tid & 1) * 2;

    auto issue_stage = [&](int kt) {
        char* st = smem + (kt & 1) * STAGE;
        const int k0 = kt << 5;
#pragma unroll
        for (int p = 0; p < 4; p++) {
            const __nv_bfloat16* src = srcs[p] + (size_t)(rowbase[p] + row) * K + k0;
#pragma unroll
            for (int c = 0; c < 2; c++) {
                int ch = ch0 + c;
                cp_async16(st + p * PIECE + (row * SPAD + ch * 8) * 2, src + ch * 8);
            }
        }
    };

    const int NK = K >> 5;
    issue_stage(0);
    CP_COMMIT();

    for (int kt = 0; kt < NK; kt++) {
        CP_WAIT0();
        __syncthreads();
        if (kt + 1 < NK) issue_stage(kt + 1);
        CP_COMMIT();

        const char* st = smem + (kt & 1) * STAGE;
        const __nv_bfloat16* pAh = (const __nv_bfloat16*)(st);
        const __nv_bfloat16* pAl = (const __nv_bfloat16*)(st + PIECE);
        const __nv_bfloat16* pBh = (const __nv_bfloat16*)(st + 2 * PIECE);
        const __nv_bfloat16* pBl = (const __nv_bfloat16*)(st + 3 * PIECE);

#pragma unroll
        for (int ks = 0; ks < 2; ks++) {
            const int ac = ks * 16 + aColOff;
            const int bc = ks * 16 + bColOff;
            uint32_t ah[2][4], al[2][4];
#pragma unroll
            for (int mi = 0; mi < 2; mi++) {
                ldsm_x4(ah[mi], pAh + (aRow + mi * 16) * SPAD + ac);
                ldsm_x4(al[mi], pAl + (aRow + mi * 16) * SPAD + ac);
            }
#pragma unroll
            for (int n2 = 0; n2 < 4; n2++) {
                const int nr = warpN * 64 + n2 * 16 + bRowOff;
                uint32_t bh[4], bl[4];
                ldsm_x4(bh, pBh + nr * SPAD + bc);
                ldsm_x4(bl, pBl + nr * SPAD + bc);
#pragma unroll
                for (int mi = 0; mi < 2; mi++) {
                    mma16816(acc[mi][2*n2],   ah[mi], bh[0], bh[1]);
                    mma16816(acc[mi][2*n2+1], ah[mi], bh[2], bh[3]);
                    mma16816(acc[mi][2*n2],   ah[mi], bl[0], bl[1]);
                    mma16816(acc[mi][2*n2+1], ah[mi], bl[2], bl[3]);
                    mma16816(acc[mi][2*n2],   al[mi], bh[0], bh[1]);
                    mma16816(acc[mi][2*n2+1], al[mi], bh[2], bh[3]);
                }
            }
        }
    }

    const int colbase = bn + warpN * 64;

    // fused softmax over 64-col heads (k region of merged qkv projection)
    if (colbase >= sm_lo && colbase < sm_hi) {
#pragma unroll
        for (int mi = 0; mi < 2; mi++) {
#pragma unroll
            for (int hf = 0; hf < 2; hf++) {
                float mx = -3.4e38f;
#pragma unroll
                for (int ni = 0; ni < 8; ni++)
                    mx = fmaxf(mx, fmaxf(acc[mi][ni][2*hf], acc[mi][ni][2*hf+1]));
                mx = fmaxf(mx, __shfl_xor_sync(0xffffffffu, mx, 1));
                mx = fmaxf(mx, __shfl_xor_sync(0xffffffffu, mx, 2));
                float s = 0.f;
#pragma unroll
                for (int ni = 0; ni < 8; ni++) {
                    float e0 = expf(acc[mi][ni][2*hf]     - mx);
                    float e1 = expf(acc[mi][ni][2*hf + 1] - mx);
                    acc[mi][ni][2*hf] = e0; acc[mi][ni][2*hf+1] = e1;
                    s += e0 + e1;
                }
                s += __shfl_xor_sync(0xffffffffu, s, 1);
                s += __shfl_xor_sync(0xffffffffu, s, 2);
                float inv = 1.f / s;
#pragma unroll
                for (int ni = 0; ni < 8; ni++) {
                    acc[mi][ni][2*hf]     *= inv;
                    acc[mi][ni][2*hf + 1] *= inv;
                }
            }
        }
    }

    // epilogue: route by column block (uniform per warp)
    float* Cp; int cb; int ldc;
    if (colbase < csplit) { Cp = C1; cb = colbase; ldc = ld1; }
    else                  { Cp = C2; cb = colbase - csplit; ldc = ld2; }

    const int g = lane >> 2, t = lane & 3;
#pragma unroll
    for (int mi = 0; mi < 2; mi++) {
        int r = bm + warpM * 32 + mi * 16 + g;
#pragma unroll
        for (int ni = 0; ni < 8; ni++) {
            int co = cb + ni * 8 + t * 2;
            float b0 = 0.f, b1 = 0.f;
            if (bias) { b0 = bias[co]; b1 = bias[co + 1]; }
            float2 v0 = {acc[mi][ni][0] + b0, acc[mi][ni][1] + b1};
            float2 v1 = {acc[mi][ni][2] + b0, acc[mi][ni][3] + b1};
            *(float2*)(Cp + (size_t)r * ldc + co)       = v0;
            *(float2*)(Cp + (size_t)(r + 8) * ldc + co) = v1;
        }
    }
}

// ---------------------------------------------------------------------------
// split x (fp32 -> bf16 hi/lo)
// ---------------------------------------------------------------------------
__global__ __launch_bounds__(256) void split_x_kernel(const float* __restrict__ x)
{
    int i = blockIdx.x * 256 + threadIdx.x;
    float4 v = ((const float4*)x)[i];
    float f[4] = {v.x, v.y, v.z, v.w};
    __nv_bfloat162 h01, h23, l01, l23;
    __nv_bfloat16 h, l;
    h = __float2bfloat16_rn(f[0]); l = __float2bfloat16_rn(f[0] - __bfloat162float(h)); h01.x = h; l01.x = l;
    h = __float2bfloat16_rn(f[1]); l = __float2bfloat16_rn(f[1] - __bfloat162float(h)); h01.y = h; l01.y = l;
    h = __float2bfloat16_rn(f[2]); l = __float2bfloat16_rn(f[2] - __bfloat162float(h)); h23.x = h; l23.x = l;
    h = __float2bfloat16_rn(f[3]); l = __float2bfloat16_rn(f[3] - __bfloat162float(h)); h23.y = h; l23.y = l;
    ((__nv_bfloat162*)g_xh)[2 * i] = h01; ((__nv_bfloat162*)g_xh)[2 * i + 1] = h23;
    ((__nv_bfloat162*)g_xl)[2 * i] = l01; ((__nv_bfloat162*)g_xl)[2 * i + 1] = l23;
}

// ---------------------------------------------------------------------------
// all-weights transpose + split (z selects which weight)
//   z=0: w_q   [768][768]   -> g_wqkv rows 0..767
//   z=1: w_kv  [768][1536]  -> g_wqkv rows 768..2303
//   z=2: w_proj[1536][768]  -> g_wp rows 0..767 (K=1536)
// ---------------------------------------------------------------------------
__global__ __launch_bounds__(256) void wsplit_all_kernel(
    const float* __restrict__ wq, const float* __restrict__ wkv,
    const float* __restrict__ wp)
{
    __shared__ float t[32][33];
    const int z = blockIdx.z;
    const float* W; __nv_bfloat16 *Th, *Tl; int K, N, roff;
    if (z == 0)      { W = wq;  K = DIMV; N = DIMV; Th = g_wqkvh; Tl = g_wqkvl; roff = 0;   }
    else if (z == 1) { W = wkv; K = DIMV; N = EDIM; Th = g_wqkvh; Tl = g_wqkvl; roff = DIMV;}
    else             { W = wp;  K = EDIM; N = DIMV; Th = g_wph;   Tl = g_wpl;   roff = 0;   }

    int n0 = blockIdx.x * 32, k0 = blockIdx.y * 32;
    if (n0 >= N || k0 >= K) return;
    int tx = threadIdx.x & 31, ty = threadIdx.x >> 5;
#pragma unroll
    for (int i = 0; i < 4; i++)
        t[ty + i * 8][tx] = W[(size_t)(k0 + ty + i * 8) * N + n0 + tx];
    __syncthreads();
#pragma unroll
    for (int i = 0; i < 4; i++) {
        float f = t[tx][ty + i * 8];
        __nv_bfloat16 h = __float2bfloat16_rn(f);
        __nv_bfloat16 l = __float2bfloat16_rn(f - __bfloat162float(h));
        Th[(size_t)(roff + n0 + ty + i * 8) * K + k0 + tx] = h;
        Tl[(size_t)(roff + n0 + ty + i * 8) * K + k0 + tx] = l;
    }
}

// ---------------------------------------------------------------------------
// ktv partials (k already softmaxed by fused GEMM epilogue)
// ---------------------------------------------------------------------------
__global__ __launch_bounds__(256) void ktv_part_kernel()
{
    int bh = blockIdx.x, s = blockIdx.y;
    int b = bh / HEADS, h = bh % HEADS;
    const int chunk = NN / KTV_SPLIT;            // 128
    const float* ksp = g_kv + (size_t)b * NN * EDIM + h * HD + (size_t)s * chunk * EDIM;
    const float* vp  = ksp + DIMV;

    __shared__ float Ks[32][64];
    __shared__ float Vs[32][64];

    int tid = threadIdx.x;
    int td = tid & 15, te = tid >> 4;
    float acc[4][4];
#pragma unroll
    for (int i = 0; i < 4; i++)
#pragma unroll
        for (int j = 0; j < 4; j++) acc[i][j] = 0.f;

    for (int n0 = 0; n0 < chunk; n0 += 32) {
#pragma unroll
        for (int i = 0; i < 2; i++) {
            int idx4 = tid + i * 256;
            int nl = idx4 >> 4, d4 = (idx4 & 15) * 4;
            *(float4*)&Ks[nl][d4] = *(const float4*)(ksp + (size_t)(n0 + nl) * EDIM + d4);
            *(float4*)&Vs[nl][d4] = *(const float4*)(vp  + (size_t)(n0 + nl) * EDIM + d4);
        }
        __syncthreads();
#pragma unroll 8
        for (int n = 0; n < 32; n++) {
            float a0[4], b0[4];
            *(float4*)a0 = *(const float4*)&Ks[n][td * 4];
            *(float4*)b0 = *(const float4*)&Vs[n][te * 4];
#pragma unroll
            for (int i = 0; i < 4; i++)
#pragma unroll
                for (int j = 0; j < 4; j++)
                    acc[i][j] += a0[i] * b0[j];
        }
        __syncthreads();
    }

    float* out = g_ktvp + ((size_t)s * 96 + bh) * HD * HD;
#pragma unroll
    for (int i = 0; i < 4; i++) {
        float4 v;
        v.x = acc[i][0]; v.y = acc[i][1]; v.z = acc[i][2]; v.w = acc[i][3];
        *(float4*)&out[(td * 4 + i) * HD + te * 4] = v;
    }
}

// reduce partials and scatter into both ektv positions (direct + rolled)
__global__ void ktv_reduce_kernel()
{
    int idx = blockIdx.x * 256 + threadIdx.x;
    float s = 0.f;
#pragma unroll
    for (int i = 0; i < KTV_SPLIT; i++)
        s += g_ktvp[(size_t)i * 96 * HD * HD + idx];

    int e = idx & 63;
    int d = (idx >> 6) & 63;
    int bh = idx >> 12;
    int h = bh % HEADS, b = bh / HEADS;
    g_ektv[(((size_t)(b * 24 + h) * 64) + d) * 64 + e] = s;
    int ct = h * 64 + e - 32;
    if (ct < 0) ct += 768;
    int j2 = 12 + (ct >> 6), e2 = ct & 63;
    g_ektv[(((size_t)(b * 24 + j2) * 64) + d) * 64 + e2] = s;
}

// ---------------------------------------------------------------------------
// Fused attn + LePE, rolling 3-slab ring over YG consecutive image rows.
// Block (yg, j, b): rows Y..Y+YG-1; per row loads ONE new q slab (16KB).
// ---------------------------------------------------------------------------
#define YG 8
#define QS_STRIDE 72
#define AL_ES   0
#define AL_QS   16384
#define AL_WT   (AL_QS + 3*64*QS_STRIDE*4)
#define AL_BS   (AL_WT + 64*9*4)
#define AL_SMEM (AL_BS + 256)

__global__ __launch_bounds__(256) void attn_lepe_kernel(
    const float* __restrict__ w_lepe, const float* __restrict__ b_lepe)
{
    extern __shared__ char sm[];
    float* Es = (float*)(sm + AL_ES);        // [64][64]
    float* Qs = (float*)(sm + AL_QS);        // [3][64][QS_STRIDE] ring
    float* Wt = (float*)(sm + AL_WT);        // [64][9]
    float* Bs = (float*)(sm + AL_BS);        // [64]

    const int Y = blockIdx.x * YG, j = blockIdx.y, b = blockIdx.z;
    const int tid = threadIdx.x;

    const float* ep = g_ektv + (size_t)((b * 24 + j) * 64) * 64;
#pragma unroll
    for (int i = 0; i < 4; i++) {
        int idx4 = tid + i * 256;
        *(float4*)&Es[idx4 * 4] = *(const float4*)(ep + idx4 * 4);
    }
    for (int idx = tid; idx < 64 * 9; idx += 256) Wt[idx] = w_lepe[(j * 64) * 9 + idx];
    if (tid < 64) Bs[tid] = b_lepe[j * 64 + tid];

    const int qbase = (j < 12) ? j * 64 : ((j - 12) * 64 + 32);

    auto load_slab = [&](int y) {
        float* dst = Qs + ((y + 1) % 3) * 64 * QS_STRIDE;
        bool valid = (y >= 0) && (y < 64);
        const float* qrow = g_q + ((size_t)(b * NN) + y * 64) * DIMV;
#pragma unroll
        for (int i = 0; i < 4; i++) {
            int idx4 = tid + i * 256;
            int x = idx4 >> 4, d4 = (idx4 & 15) * 4;
            float4 v = make_float4(0.f, 0.f, 0.f, 0.f);
            if (valid) {
                int c = qbase + d4;
                if (c >= 768) c -= 768;
                v = *(const float4*)(qrow + (size_t)x * DIMV + c);
            }
            *(float4*)&dst[x * QS_STRIDE + d4] = v;
        }
    };

    load_slab(Y - 1);
    load_slab(Y);

    const int r0 = (tid >> 4) * 4, e0 = (tid & 15) * 4;

    for (int yi = 0; yi < YG; yi++) {
        const int y0 = Y + yi;
        load_slab(y0 + 1);
        __syncthreads();

        const float* Qc = Qs + ((y0 + 1) % 3) * 64 * QS_STRIDE;  // center slab
        float acc[4][4];
#pragma unroll
        for (int i = 0; i < 4; i++)
#pragma unroll
            for (int jj = 0; jj < 4; jj++) acc[i][jj] = 0.f;

#pragma unroll 8
        for (int d = 0; d < 64; d++) {
            float a0[4], b0[4];
            a0[0] = Qc[(r0 + 0) * QS_STRIDE + d];
            a0[1] = Qc[(r0 + 1) * QS_STRIDE + d];
            a0[2] = Qc[(r0 + 2) * QS_STRIDE + d];
            a0[3] = Qc[(r0 + 3) * QS_STRIDE + d];
            *(float4*)b0 = *(const float4*)&Es[d * 64 + e0];
#pragma unroll
            for (int i = 0; i < 4; i++)
#pragma unroll
                for (int jj = 0; jj < 4; jj++)
                    acc[i][jj] += a0[i] * b0[jj];
        }

        const float* slab0 = Qs + ((y0 + 0) % 3) * 64 * QS_STRIDE;  // row y0-1
        const float* slab1 = Qc;                                    // row y0
        const float* slab2 = Qs + ((y0 + 2) % 3) * 64 * QS_STRIDE;  // row y0+1
        const float* slabs[3] = {slab0, slab1, slab2};

        const int n0 = y0 * 64;
#pragma unroll
        for (int i = 0; i < 4; i++) {
            const int x = r0 + i;
            uint32_t hp[2], lp[2];
#pragma unroll
            for (int jj = 0; jj < 4; jj++) {
                const int e = e0 + jj;
                float sum = Bs[e];
#pragma unroll
                for (int ky = 0; ky < 3; ky++) {
#pragma unroll
                    for (int kx = 0; kx < 3; kx++) {
                        int xx = x + kx - 1;
                        float qv = (xx >= 0 && xx < 64) ? slabs[ky][xx * QS_STRIDE + e] : 0.f;
                        sum += Wt[e * 9 + ky * 3 + kx] * qv;
                    }
                }
                float val = 0.125f * acc[i][jj] + sum;
                __nv_bfloat16 h = __float2bfloat16_rn(val);
                __nv_bfloat16 l = __float2bfloat16_rn(val - __bfloat162float(h));
                ((__nv_bfloat16*)hp)[jj] = h;
                ((__nv_bfloat16*)lp)[jj] = l;
            }
            size_t off = ((size_t)(b * NN) + n0 + x) * EDIM + j * 64 + e0;
            *(uint2*)(g_yh + off) = make_uint2(hp[0], hp[1]);
            *(uint2*)(g_yl + off) = make_uint2(lp[0], lp[1]);
        }
        __syncthreads();   // protect oldest slab before next load overwrites it
    }
}

// ---------------------------------------------------------------------------
extern "C" void kernel_launch(void* const* d_in, const int* in_sizes, int n_in,
                              void* d_out, int out_size)
{
    const float* x      = (const float*)d_in[0];
    const float* w_q    = (const float*)d_in[1];
    const float* w_kv   = (const float*)d_in[2];
    const float* w_proj = (const float*)d_in[3];
    const float* b_proj = (const float*)d_in[4];
    const float* w_lepe = (const float*)d_in[5];
    const float* b_lepe = (const float*)d_in[6];
    float* out = (float*)d_out;

    float* q = nullptr; float* kv = nullptr;
    cudaGetSymbolAddress((void**)&q,  g_q);
    cudaGetSymbolAddress((void**)&kv, g_kv);
    __nv_bfloat16 *xh, *xl, *yh, *yl, *wh, *wl, *wph, *wpl;
    cudaGetSymbolAddress((void**)&xh, g_xh);   cudaGetSymbolAddress((void**)&xl, g_xl);
    cudaGetSymbolAddress((void**)&yh, g_yh);   cudaGetSymbolAddress((void**)&yl, g_yl);
    cudaGetSymbolAddress((void**)&wh, g_wqkvh); cudaGetSymbolAddress((void**)&wl, g_wqkvl);
    cudaGetSymbolAddress((void**)&wph, g_wph); cudaGetSymbolAddress((void**)&wpl, g_wpl);

    static bool attr_set = false;
    if (!attr_set) {
        cudaFuncSetAttribute(gemm_mma, cudaFuncAttributeMaxDynamicSharedMemorySize, GEMM_DSMEM);
        cudaFuncSetAttribute(attn_lepe_kernel, cudaFuncAttributeMaxDynamicSharedMemorySize, AL_SMEM);
        attr_set = true;
    }

    // 0-1: operand splits
    split_x_kernel<<<(MTOT * DIMV / 4) / 256, 256>>>(x);
    wsplit_all_kernel<<<dim3(48, 48, 3), 256>>>(w_q, w_kv, w_proj);

    // 2: merged q|kv projection with fused k-softmax on cols [768,1536)
    gemm_mma<<<dim3(NQKV / 128, MTOT / 128), 256, GEMM_DSMEM>>>(
        xh, xl, wh, wl, q, kv, DIMV, DIMV, EDIM,
        MTOT, NQKV, DIMV, nullptr, DIMV, 2 * DIMV);

    // 3-4: K^T V split + reduce (scatters into ektv)
    ktv_part_kernel<<<dim3(BB * HEADS, KTV_SPLIT), 256>>>();
    ktv_reduce_kernel<<<(BB * HEADS * HD * HD) / 256, 256>>>();

    // 5: fused attn + LePE (rolling slabs) -> yh/yl
    attn_lepe_kernel<<<dim3(64 / YG, 24, BB), 256, AL_SMEM>>>(w_lepe, b_lepe);

    // 6: output projection + bias
    gemm_mma<<<dim3(DIMV / 128, MTOT / 128), 256, GEMM_DSMEM>>>(
        yh, yl, wph, wpl, out, out, DIMV, DIMV, DIMV,
        MTOT, DIMV, EDIM, b_proj, 0, 0);
}

// round 9
// speedup vs baseline: 2.5377x; 1.0005x over previous
#include <cuda_runtime.h>
#include <cuda_bf16.h>
#include <cstdint>

// Problem constants
#define BB    8
#define NN    4096
#define DIMV  768
#define HEADS 12
#define HD    64
#define EDIM  1536
#define MTOT  (BB*NN)   // 32768
#define KTV_SPLIT 32
#define NQKV  2304      // merged q|kv output width

// Scratch (static device allocations)
__device__ float g_q   [(size_t)MTOT * DIMV];
__device__ float g_kv  [(size_t)MTOT * EDIM];   // k cols 0..767 softmaxed (fused)
__device__ float g_ktvp[(size_t)KTV_SPLIT * BB * HEADS * HD * HD];
__device__ float g_ektv[BB * 2*HEADS * HD * HD];

// bf16 hi/lo split operands
__device__ __nv_bfloat16 g_xh[(size_t)MTOT * DIMV];
__device__ __nv_bfloat16 g_xl[(size_t)MTOT * DIMV];
__device__ __nv_bfloat16 g_yh[(size_t)MTOT * EDIM];
__device__ __nv_bfloat16 g_yl[(size_t)MTOT * EDIM];
// weights transposed to [N][K] + split; q|kv merged
__device__ __nv_bfloat16 g_wqkvh[NQKV * DIMV];
__device__ __nv_bfloat16 g_wqkvl[NQKV * DIMV];
__device__ __nv_bfloat16 g_wph  [DIMV * EDIM];
__device__ __nv_bfloat16 g_wpl  [DIMV * EDIM];

// ---------------------------------------------------------------------------
// MMA / cp.async helpers
// ---------------------------------------------------------------------------
__device__ __forceinline__ void ldsm_x4(uint32_t r[4], const __nv_bfloat16* p) {
    uint32_t a = (uint32_t)__cvta_generic_to_shared(p);
    asm volatile("ldmatrix.sync.aligned.m8n8.x4.shared.b16 {%0,%1,%2,%3}, [%4];"
                 : "=r"(r[0]), "=r"(r[1]), "=r"(r[2]), "=r"(r[3]) : "r"(a));
}
__device__ __forceinline__ void mma16816(float c[4], const uint32_t a[4],
                                         uint32_t b0, uint32_t b1) {
    asm volatile(
        "mma.sync.aligned.m16n8k16.row.col.f32.bf16.bf16.f32 "
        "{%0,%1,%2,%3}, {%4,%5,%6,%7}, {%8,%9}, {%0,%1,%2,%3};"
        : "+f"(c[0]), "+f"(c[1]), "+f"(c[2]), "+f"(c[3])
        : "r"(a[0]), "r"(a[1]), "r"(a[2]), "r"(a[3]), "r"(b0), "r"(b1));
}
__device__ __forceinline__ void cp_async16(void* smem_dst, const void* gsrc) {
    uint32_t a = (uint32_t)__cvta_generic_to_shared(smem_dst);
    asm volatile("cp.async.cg.shared.global [%0], [%1], 16;" :: "r"(a), "l"(gsrc));
}
#define CP_COMMIT() asm volatile("cp.async.commit_group;" ::: "memory")
#define CP_WAIT0()  asm volatile("cp.async.wait_group 0;" ::: "memory")

#define SPAD   40
#define PIECE  (128 * SPAD * 2)        // 10240 B
#define STAGE  (4 * PIECE)
#define GEMM_DSMEM (2 * STAGE)         // 81920 B

// ---------------------------------------------------------------------------
// bf16x3 tensor-core GEMM, pre-split operands, cp.async double-buffered.
// C routed by column: col < csplit -> C1 (ld1), else C2 (ld2, col-csplit).
// Softmax over 64-col heads applied for cols in [sm_lo, sm_hi).
// ---------------------------------------------------------------------------
__global__ __launch_bounds__(256, 2) void gemm_mma(
    const __nv_bfloat16* __restrict__ Ah, const __nv_bfloat16* __restrict__ Al,
    const __nv_bfloat16* __restrict__ Bh, const __nv_bfloat16* __restrict__ Bl,
    float* __restrict__ C1, float* __restrict__ C2, int csplit, int ld1, int ld2,
    int M, int N, int K, const float* __restrict__ bias, int sm_lo, int sm_hi)
{
    extern __shared__ char smem[];

    const int tid  = threadIdx.x;
    const int lane = tid & 31;
    const int warp = tid >> 5;
    const int warpM = warp >> 1;
    const int warpN = warp & 1;
    const int bm = blockIdx.y * 128;
    const int bn = blockIdx.x * 128;

    float acc[2][8][4];
#pragma unroll
    for (int i = 0; i < 2; i++)
#pragma unroll
        for (int j = 0; j < 8; j++)
#pragma unroll
            for (int l = 0; l < 4; l++) acc[i][j][l] = 0.f;

    const int aRow = warpM * 32 + (lane & 7) + ((lane & 8) ? 8 : 0);
    const int aColOff = (lane & 16) ? 8 : 0;
    const int bRowOff = (lane & 7) + ((lane & 16) ? 8 : 0);
    const int bColOff = (lane & 8) ? 8 : 0;

    const __nv_bfloat16* srcs[4] = {Ah, Al, Bh, Bl};
    const int rowbase[4] = {bm, bm, bn, bn};
    const int row = tid >> 1;
    const int ch0 = (tid & 1) * 2;

    auto issue_stage = [&](int kt) {
        char* st = smem + (kt & 1) * STAGE;
        const int k0 = kt << 5;
#pragma unroll
        for (int p = 0; p < 4; p++) {
            const __nv_bfloat16* src = srcs[p] + (size_t)(rowbase[p] + row) * K + k0;
#pragma unroll
            for (int c = 0; c < 2; c++) {
                int ch = ch0 + c;
                cp_async16(st + p * PIECE + (row * SPAD + ch * 8) * 2, src + ch * 8);
            }
        }
    };

    const int NK = K >> 5;
    issue_stage(0);
    CP_COMMIT();

    for (int kt = 0; kt < NK; kt++) {
        CP_WAIT0();
        __syncthreads();
        if (kt + 1 < NK) issue_stage(kt + 1);
        CP_COMMIT();

        const char* st = smem + (kt & 1) * STAGE;
        const __nv_bfloat16* pAh = (const __nv_bfloat16*)(st);
        const __nv_bfloat16* pAl = (const __nv_bfloat16*)(st + PIECE);
        const __nv_bfloat16* pBh = (const __nv_bfloat16*)(st + 2 * PIECE);
        const __nv_bfloat16* pBl = (const __nv_bfloat16*)(st + 3 * PIECE);

#pragma unroll
        for (int ks = 0; ks < 2; ks++) {
            const int ac = ks * 16 + aColOff;
            const int bc = ks * 16 + bColOff;
            uint32_t ah[2][4], al[2][4];
#pragma unroll
            for (int mi = 0; mi < 2; mi++) {
                ldsm_x4(ah[mi], pAh + (aRow + mi * 16) * SPAD + ac);
                ldsm_x4(al[mi], pAl + (aRow + mi * 16) * SPAD + ac);
            }
#pragma unroll
            for (int n2 = 0; n2 < 4; n2++) {
                const int nr = warpN * 64 + n2 * 16 + bRowOff;
                uint32_t bh[4], bl[4];
                ldsm_x4(bh, pBh + nr * SPAD + bc);
                ldsm_x4(bl, pBl + nr * SPAD + bc);
#pragma unroll
                for (int mi = 0; mi < 2; mi++) {
                    mma16816(acc[mi][2*n2],   ah[mi], bh[0], bh[1]);
                    mma16816(acc[mi][2*n2+1], ah[mi], bh[2], bh[3]);
                    mma16816(acc[mi][2*n2],   ah[mi], bl[0], bl[1]);
                    mma16816(acc[mi][2*n2+1], ah[mi], bl[2], bl[3]);
                    mma16816(acc[mi][2*n2],   al[mi], bh[0], bh[1]);
                    mma16816(acc[mi][2*n2+1], al[mi], bh[2], bh[3]);
                }
            }
        }
    }

    const int colbase = bn + warpN * 64;

    // fused softmax over 64-col heads (k region of merged qkv projection)
    if (colbase >= sm_lo && colbase < sm_hi) {
#pragma unroll
        for (int mi = 0; mi < 2; mi++) {
#pragma unroll
            for (int hf = 0; hf < 2; hf++) {
                float mx = -3.4e38f;
#pragma unroll
                for (int ni = 0; ni < 8; ni++)
                    mx = fmaxf(mx, fmaxf(acc[mi][ni][2*hf], acc[mi][ni][2*hf+1]));
                mx = fmaxf(mx, __shfl_xor_sync(0xffffffffu, mx, 1));
                mx = fmaxf(mx, __shfl_xor_sync(0xffffffffu, mx, 2));
                float s = 0.f;
#pragma unroll
                for (int ni = 0; ni < 8; ni++) {
                    float e0 = expf(acc[mi][ni][2*hf]     - mx);
                    float e1 = expf(acc[mi][ni][2*hf + 1] - mx);
                    acc[mi][ni][2*hf] = e0; acc[mi][ni][2*hf+1] = e1;
                    s += e0 + e1;
                }
                s += __shfl_xor_sync(0xffffffffu, s, 1);
                s += __shfl_xor_sync(0xffffffffu, s, 2);
                float inv = 1.f / s;
#pragma unroll
                for (int ni = 0; ni < 8; ni++) {
                    acc[mi][ni][2*hf]     *= inv;
                    acc[mi][ni][2*hf + 1] *= inv;
                }
            }
        }
    }

    // epilogue: route by column block (uniform per warp)
    float* Cp; int cb; int ldc;
    if (colbase < csplit) { Cp = C1; cb = colbase; ldc = ld1; }
    else                  { Cp = C2; cb = colbase - csplit; ldc = ld2; }

    const int g = lane >> 2, t = lane & 3;
#pragma unroll
    for (int mi = 0; mi < 2; mi++) {
        int r = bm + warpM * 32 + mi * 16 + g;
#pragma unroll
        for (int ni = 0; ni < 8; ni++) {
            int co = cb + ni * 8 + t * 2;
            float b0 = 0.f, b1 = 0.f;
            if (bias) { b0 = bias[co]; b1 = bias[co + 1]; }
            float2 v0 = {acc[mi][ni][0] + b0, acc[mi][ni][1] + b1};
            float2 v1 = {acc[mi][ni][2] + b0, acc[mi][ni][3] + b1};
            *(float2*)(Cp + (size_t)r * ldc + co)       = v0;
            *(float2*)(Cp + (size_t)(r + 8) * ldc + co) = v1;
        }
    }
}

// ---------------------------------------------------------------------------
// split x (fp32 -> bf16 hi/lo)
// ---------------------------------------------------------------------------
__global__ __launch_bounds__(256) void split_x_kernel(const float* __restrict__ x)
{
    int i = blockIdx.x * 256 + threadIdx.x;
    float4 v = ((const float4*)x)[i];
    float f[4] = {v.x, v.y, v.z, v.w};
    __nv_bfloat162 h01, h23, l01, l23;
    __nv_bfloat16 h, l;
    h = __float2bfloat16_rn(f[0]); l = __float2bfloat16_rn(f[0] - __bfloat162float(h)); h01.x = h; l01.x = l;
    h = __float2bfloat16_rn(f[1]); l = __float2bfloat16_rn(f[1] - __bfloat162float(h)); h01.y = h; l01.y = l;
    h = __float2bfloat16_rn(f[2]); l = __float2bfloat16_rn(f[2] - __bfloat162float(h)); h23.x = h; l23.x = l;
    h = __float2bfloat16_rn(f[3]); l = __float2bfloat16_rn(f[3] - __bfloat162float(h)); h23.y = h; l23.y = l;
    ((__nv_bfloat162*)g_xh)[2 * i] = h01; ((__nv_bfloat162*)g_xh)[2 * i + 1] = h23;
    ((__nv_bfloat162*)g_xl)[2 * i] = l01; ((__nv_bfloat162*)g_xl)[2 * i + 1] = l23;
}

// ---------------------------------------------------------------------------
// all-weights transpose + split (z selects which weight)
//   z=0: w_q   [768][768]   -> g_wqkv rows 0..767
//   z=1: w_kv  [768][1536]  -> g_wqkv rows 768..2303
//   z=2: w_proj[1536][768]  -> g_wp rows 0..767 (K=1536)
// ---------------------------------------------------------------------------
__global__ __launch_bounds__(256) void wsplit_all_kernel(
    const float* __restrict__ wq, const float* __restrict__ wkv,
    const float* __restrict__ wp)
{
    __shared__ float t[32][33];
    const int z = blockIdx.z;
    const float* W; __nv_bfloat16 *Th, *Tl; int K, N, roff;
    if (z == 0)      { W = wq;  K = DIMV; N = DIMV; Th = g_wqkvh; Tl = g_wqkvl; roff = 0;   }
    else if (z == 1) { W = wkv; K = DIMV; N = EDIM; Th = g_wqkvh; Tl = g_wqkvl; roff = DIMV;}
    else             { W = wp;  K = EDIM; N = DIMV; Th = g_wph;   Tl = g_wpl;   roff = 0;   }

    int n0 = blockIdx.x * 32, k0 = blockIdx.y * 32;
    if (n0 >= N || k0 >= K) return;
    int tx = threadIdx.x & 31, ty = threadIdx.x >> 5;
#pragma unroll
    for (int i = 0; i < 4; i++)
        t[ty + i * 8][tx] = W[(size_t)(k0 + ty + i * 8) * N + n0 + tx];
    __syncthreads();
#pragma unroll
    for (int i = 0; i < 4; i++) {
        float f = t[tx][ty + i * 8];
        __nv_bfloat16 h = __float2bfloat16_rn(f);
        __nv_bfloat16 l = __float2bfloat16_rn(f - __bfloat162float(h));
        Th[(size_t)(roff + n0 + ty + i * 8) * K + k0 + tx] = h;
        Tl[(size_t)(roff + n0 + ty + i * 8) * K + k0 + tx] = l;
    }
}

// ---------------------------------------------------------------------------
// ktv partials (k already softmaxed by fused GEMM epilogue)
// ---------------------------------------------------------------------------
__global__ __launch_bounds__(256) void ktv_part_kernel()
{
    int bh = blockIdx.x, s = blockIdx.y;
    int b = bh / HEADS, h = bh % HEADS;
    const int chunk = NN / KTV_SPLIT;            // 128
    const float* ksp = g_kv + (size_t)b * NN * EDIM + h * HD + (size_t)s * chunk * EDIM;
    const float* vp  = ksp + DIMV;

    __shared__ float Ks[32][64];
    __shared__ float Vs[32][64];

    int tid = threadIdx.x;
    int td = tid & 15, te = tid >> 4;
    float acc[4][4];
#pragma unroll
    for (int i = 0; i < 4; i++)
#pragma unroll
        for (int j = 0; j < 4; j++) acc[i][j] = 0.f;

    for (int n0 = 0; n0 < chunk; n0 += 32) {
#pragma unroll
        for (int i = 0; i < 2; i++) {
            int idx4 = tid + i * 256;
            int nl = idx4 >> 4, d4 = (idx4 & 15) * 4;
            *(float4*)&Ks[nl][d4] = *(const float4*)(ksp + (size_t)(n0 + nl) * EDIM + d4);
            *(float4*)&Vs[nl][d4] = *(const float4*)(vp  + (size_t)(n0 + nl) * EDIM + d4);
        }
        __syncthreads();
#pragma unroll 8
        for (int n = 0; n < 32; n++) {
            float a0[4], b0[4];
            *(float4*)a0 = *(const float4*)&Ks[n][td * 4];
            *(float4*)b0 = *(const float4*)&Vs[n][te * 4];
#pragma unroll
            for (int i = 0; i < 4; i++)
#pragma unroll
                for (int j = 0; j < 4; j++)
                    acc[i][j] += a0[i] * b0[j];
        }
        __syncthreads();
    }

    float* out = g_ktvp + ((size_t)s * 96 + bh) * HD * HD;
#pragma unroll
    for (int i = 0; i < 4; i++) {
        float4 v;
        v.x = acc[i][0]; v.y = acc[i][1]; v.z = acc[i][2]; v.w = acc[i][3];
        *(float4*)&out[(td * 4 + i) * HD + te * 4] = v;
    }
}

// reduce partials and scatter into both ektv positions (direct + rolled)
__global__ void ktv_reduce_kernel()
{
    int idx = blockIdx.x * 256 + threadIdx.x;
    float s = 0.f;
#pragma unroll
    for (int i = 0; i < KTV_SPLIT; i++)
        s += g_ktvp[(size_t)i * 96 * HD * HD + idx];

    int e = idx & 63;
    int d = (idx >> 6) & 63;
    int bh = idx >> 12;
    int h = bh % HEADS, b = bh / HEADS;
    g_ektv[(((size_t)(b * 24 + h) * 64) + d) * 64 + e] = s;
    int ct = h * 64 + e - 32;
    if (ct < 0) ct += 768;
    int j2 = 12 + (ct >> 6), e2 = ct & 63;
    g_ektv[(((size_t)(b * 24 + j2) * 64) + d) * 64 + e2] = s;
}

// ---------------------------------------------------------------------------
// Fused attn + LePE, rolling 3-slab ring over YG consecutive image rows.
// Block (yg, j, b): rows Y..Y+YG-1; per row loads ONE new q slab (16KB).
// ---------------------------------------------------------------------------
#define YG 8
#define QS_STRIDE 72
#define AL_ES   0
#define AL_QS   16384
#define AL_WT   (AL_QS + 3*64*QS_STRIDE*4)
#define AL_BS   (AL_WT + 64*9*4)
#define AL_SMEM (AL_BS + 256)

__global__ __launch_bounds__(256) void attn_lepe_kernel(
    const float* __restrict__ w_lepe, const float* __restrict__ b_lepe)
{
    extern __shared__ char sm[];
    float* Es = (float*)(sm + AL_ES);        // [64][64]
    float* Qs = (float*)(sm + AL_QS);        // [3][64][QS_STRIDE] ring
    float* Wt = (float*)(sm + AL_WT);        // [64][9]
    float* Bs = (float*)(sm + AL_BS);        // [64]

    const int Y = blockIdx.x * YG, j = blockIdx.y, b = blockIdx.z;
    const int tid = threadIdx.x;

    const float* ep = g_ektv + (size_t)((b * 24 + j) * 64) * 64;
#pragma unroll
    for (int i = 0; i < 4; i++) {
        int idx4 = tid + i * 256;
        *(float4*)&Es[idx4 * 4] = *(const float4*)(ep + idx4 * 4);
    }
    for (int idx = tid; idx < 64 * 9; idx += 256) Wt[idx] = w_lepe[(j * 64) * 9 + idx];
    if (tid < 64) Bs[tid] = b_lepe[j * 64 + tid];

    const int qbase = (j < 12) ? j * 64 : ((j - 12) * 64 + 32);

    auto load_slab = [&](int y) {
        float* dst = Qs + ((y + 1) % 3) * 64 * QS_STRIDE;
        bool valid = (y >= 0) && (y < 64);
        const float* qrow = g_q + ((size_t)(b * NN) + y * 64) * DIMV;
#pragma unroll
        for (int i = 0; i < 4; i++) {
            int idx4 = tid + i * 256;
            int x = idx4 >> 4, d4 = (idx4 & 15) * 4;
            float4 v = make_float4(0.f, 0.f, 0.f, 0.f);
            if (valid) {
                int c = qbase + d4;
                if (c >= 768) c -= 768;
                v = *(const float4*)(qrow + (size_t)x * DIMV + c);
            }
            *(float4*)&dst[x * QS_STRIDE + d4] = v;
        }
    };

    load_slab(Y - 1);
    load_slab(Y);

    const int r0 = (tid >> 4) * 4, e0 = (tid & 15) * 4;

    for (int yi = 0; yi < YG; yi++) {
        const int y0 = Y + yi;
        load_slab(y0 + 1);
        __syncthreads();

        const float* Qc = Qs + ((y0 + 1) % 3) * 64 * QS_STRIDE;  // center slab
        float acc[4][4];
#pragma unroll
        for (int i = 0; i < 4; i++)
#pragma unroll
            for (int jj = 0; jj < 4; jj++) acc[i][jj] = 0.f;

#pragma unroll 8
        for (int d = 0; d < 64; d++) {
            float a0[4], b0[4];
            a0[0] = Qc[(r0 + 0) * QS_STRIDE + d];
            a0[1] = Qc[(r0 + 1) * QS_STRIDE + d];
            a0[2] = Qc[(r0 + 2) * QS_STRIDE + d];
            a0[3] = Qc[(r0 + 3) * QS_STRIDE + d];
            *(float4*)b0 = *(const float4*)&Es[d * 64 + e0];
#pragma unroll
            for (int i = 0; i < 4; i++)
#pragma unroll
                for (int jj = 0; jj < 4; jj++)
                    acc[i][jj] += a0[i] * b0[jj];
        }

        const float* slab0 = Qs + ((y0 + 0) % 3) * 64 * QS_STRIDE;  // row y0-1
        const float* slab1 = Qc;                                    // row y0
        const float* slab2 = Qs + ((y0 + 2) % 3) * 64 * QS_STRIDE;  // row y0+1
        const float* slabs[3] = {slab0, slab1, slab2};

        const int n0 = y0 * 64;
#pragma unroll
        for (int i = 0; i < 4; i++) {
            const int x = r0 + i;
            uint32_t hp[2], lp[2];
#pragma unroll
            for (int jj = 0; jj < 4; jj++) {
                const int e = e0 + jj;
                float sum = Bs[e];
#pragma unroll
                for (int ky = 0; ky < 3; ky++) {
#pragma unroll
                    for (int kx = 0; kx < 3; kx++) {
                        int xx = x + kx - 1;
                        float qv = (xx >= 0 && xx < 64) ? slabs[ky][xx * QS_STRIDE + e] : 0.f;
                        sum += Wt[e * 9 + ky * 3 + kx] * qv;
                    }
                }
                float val = 0.125f * acc[i][jj] + sum;
                __nv_bfloat16 h = __float2bfloat16_rn(val);
                __nv_bfloat16 l = __float2bfloat16_rn(val - __bfloat162float(h));
                ((__nv_bfloat16*)hp)[jj] = h;
                ((__nv_bfloat16*)lp)[jj] = l;
            }
            size_t off = ((size_t)(b * NN) + n0 + x) * EDIM + j * 64 + e0;
            *(uint2*)(g_yh + off) = make_uint2(hp[0], hp[1]);
            *(uint2*)(g_yl + off) = make_uint2(lp[0], lp[1]);
        }
        __syncthreads();   // protect oldest slab before next load overwrites it
    }
}

// ---------------------------------------------------------------------------
extern "C" void kernel_launch(void* const* d_in, const int* in_sizes, int n_in,
                              void* d_out, int out_size)
{
    const float* x      = (const float*)d_in[0];
    const float* w_q    = (const float*)d_in[1];
    const float* w_kv   = (const float*)d_in[2];
    const float* w_proj = (const float*)d_in[3];
    const float* b_proj = (const float*)d_in[4];
    const float* w_lepe = (const float*)d_in[5];
    const float* b_lepe = (const float*)d_in[6];
    float* out = (float*)d_out;

    float* q = nullptr; float* kv = nullptr;
    cudaGetSymbolAddress((void**)&q,  g_q);
    cudaGetSymbolAddress((void**)&kv, g_kv);
    __nv_bfloat16 *xh, *xl, *yh, *yl, *wh, *wl, *wph, *wpl;
    cudaGetSymbolAddress((void**)&xh, g_xh);   cudaGetSymbolAddress((void**)&xl, g_xl);
    cudaGetSymbolAddress((void**)&yh, g_yh);   cudaGetSymbolAddress((void**)&yl, g_yl);
    cudaGetSymbolAddress((void**)&wh, g_wqkvh); cudaGetSymbolAddress((void**)&wl, g_wqkvl);
    cudaGetSymbolAddress((void**)&wph, g_wph); cudaGetSymbolAddress((void**)&wpl, g_wpl);

    static bool attr_set = false;
    if (!attr_set) {
        cudaFuncSetAttribute(gemm_mma, cudaFuncAttributeMaxDynamicSharedMemorySize, GEMM_DSMEM);
        cudaFuncSetAttribute(attn_lepe_kernel, cudaFuncAttributeMaxDynamicSharedMemorySize, AL_SMEM);
        attr_set = true;
    }

    // 0-1: operand splits
    split_x_kernel<<<(MTOT * DIMV / 4) / 256, 256>>>(x);
    wsplit_all_kernel<<<dim3(48, 48, 3), 256>>>(w_q, w_kv, w_proj);

    // 2: merged q|kv projection with fused k-softmax on cols [768,1536)
    gemm_mma<<<dim3(NQKV / 128, MTOT / 128), 256, GEMM_DSMEM>>>(
        xh, xl, wh, wl, q, kv, DIMV, DIMV, EDIM,
        MTOT, NQKV, DIMV, nullptr, DIMV, 2 * DIMV);

    // 3-4: K^T V split + reduce (scatters into ektv)
    ktv_part_kernel<<<dim3(BB * HEADS, KTV_SPLIT), 256>>>();
    ktv_reduce_kernel<<<(BB * HEADS * HD * HD) / 256, 256>>>();

    // 5: fused attn + LePE (rolling slabs) -> yh/yl
    attn_lepe_kernel<<<dim3(64 / YG, 24, BB), 256, AL_SMEM>>>(w_lepe, b_lepe);

    // 6: output projection + bias
    gemm_mma<<<dim3(DIMV / 128, MTOT / 128), 256, GEMM_DSMEM>>>(
        yh, yl, wph, wpl, out, out, DIMV, DIMV, DIMV,
        MTOT, DIMV, EDIM, b_proj, 0, 0);
}

// round 10
// speedup vs baseline: 2.5964x; 1.0232x over previous
#include <cuda_runtime.h>
#include <cuda_bf16.h>
#include <cstdint>

// Problem constants
#define BB    8
#define NN    4096
#define DIMV  768
#define HEADS 12
#define HD    64
#define EDIM  1536
#define MTOT  (BB*NN)   // 32768
#define KTV_SPLIT 32
#define NQKV  2304      // merged q|kv output width

// Scratch (static device allocations)
__device__ float g_q   [(size_t)MTOT * DIMV];
__device__ float g_kv  [(size_t)MTOT * EDIM];   // k cols 0..767 softmaxed (fused)
__device__ float g_ktvp[(size_t)KTV_SPLIT * BB * HEADS * HD * HD];
__device__ float g_ektv[BB * 2*HEADS * HD * HD];

// bf16 hi/lo split operands
__device__ __nv_bfloat16 g_xh[(size_t)MTOT * DIMV];
__device__ __nv_bfloat16 g_xl[(size_t)MTOT * DIMV];
__device__ __nv_bfloat16 g_yh[(size_t)MTOT * EDIM];
__device__ __nv_bfloat16 g_yl[(size_t)MTOT * EDIM];
// weights transposed to [N][K] + split; q|kv merged
__device__ __nv_bfloat16 g_wqkvh[NQKV * DIMV];
__device__ __nv_bfloat16 g_wqkvl[NQKV * DIMV];
__device__ __nv_bfloat16 g_wph  [DIMV * EDIM];
__device__ __nv_bfloat16 g_wpl  [DIMV * EDIM];

// ---------------------------------------------------------------------------
// MMA / cp.async helpers
// ---------------------------------------------------------------------------
__device__ __forceinline__ void ldsm_x4p(uint32_t r[4], const void* p) {
    uint32_t a = (uint32_t)__cvta_generic_to_shared(p);
    asm volatile("ldmatrix.sync.aligned.m8n8.x4.shared.b16 {%0,%1,%2,%3}, [%4];"
                 : "=r"(r[0]), "=r"(r[1]), "=r"(r[2]), "=r"(r[3]) : "r"(a));
}
__device__ __forceinline__ void mma16816(float c[4], const uint32_t a[4],
                                         uint32_t b0, uint32_t b1) {
    asm volatile(
        "mma.sync.aligned.m16n8k16.row.col.f32.bf16.bf16.f32 "
        "{%0,%1,%2,%3}, {%4,%5,%6,%7}, {%8,%9}, {%0,%1,%2,%3};"
        : "+f"(c[0]), "+f"(c[1]), "+f"(c[2]), "+f"(c[3])
        : "r"(a[0]), "r"(a[1]), "r"(a[2]), "r"(a[3]), "r"(b0), "r"(b1));
}
__device__ __forceinline__ void cp_async16(void* smem_dst, const void* gsrc) {
    uint32_t a = (uint32_t)__cvta_generic_to_shared(smem_dst);
    asm volatile("cp.async.cg.shared.global [%0], [%1], 16;" :: "r"(a), "l"(gsrc));
}
#define CP_COMMIT() asm volatile("cp.async.commit_group;" ::: "memory")
#define CP_WAIT0()  asm volatile("cp.async.wait_group 0;" ::: "memory")
#define CP_WAIT1()  asm volatile("cp.async.wait_group 1;" ::: "memory")

// SW128 swizzle on (row, 16B-chunk) within a 128x32 bf16 tile (64 B rows)
__device__ __forceinline__ int sw_off(int row, int chunk) {
    int byte = row * 64 + chunk * 16;
    return byte ^ ((byte >> 3) & 0x70);
}

#define TILE_SW  8192                 // one 128x32 bf16 tile, swizzled, no pad
#define STAGE_SW (4 * TILE_SW)        // Ah, Al, Bh, Bl  = 32768 B
#define NSTAGE   3
#define GEMM_DSMEM (NSTAGE * STAGE_SW)  // 98304 B

// ---------------------------------------------------------------------------
// bf16x3 tensor-core GEMM, pre-split operands, 3-stage cp.async pipeline
// (wait_group 1 => prefetch depth 2). 128x128 tile, BK=32, 2 CTAs/SM.
// C routed by column: col < csplit -> C1 (ld1), else C2 (ld2, col-csplit).
// Softmax over 64-col heads applied for cols in [sm_lo, sm_hi).
// ---------------------------------------------------------------------------
__global__ __launch_bounds__(256, 2) void gemm_mma(
    const __nv_bfloat16* __restrict__ Ah, const __nv_bfloat16* __restrict__ Al,
    const __nv_bfloat16* __restrict__ Bh, const __nv_bfloat16* __restrict__ Bl,
    float* __restrict__ C1, float* __restrict__ C2, int csplit, int ld1, int ld2,
    int M, int N, int K, const float* __restrict__ bias, int sm_lo, int sm_hi)
{
    extern __shared__ char smem[];

    const int tid  = threadIdx.x;
    const int lane = tid & 31;
    const int warp = tid >> 5;
    const int warpM = warp >> 1;
    const int warpN = warp & 1;
    const int bm = blockIdx.y * 128;
    const int bn = blockIdx.x * 128;

    float acc[2][8][4];
#pragma unroll
    for (int i = 0; i < 2; i++)
#pragma unroll
        for (int j = 0; j < 8; j++)
#pragma unroll
            for (int l = 0; l < 4; l++) acc[i][j][l] = 0.f;

    const int aRow = warpM * 32 + (lane & 7) + ((lane & 8) ? 8 : 0);
    const int bRow = warpN * 64 + (lane & 7) + ((lane & 16) ? 8 : 0);

    // precomputed swizzled ldsm offsets (loop-invariant; only stage base moves)
    int offA[2][2], offB[4][2];
#pragma unroll
    for (int mi = 0; mi < 2; mi++)
#pragma unroll
        for (int ks = 0; ks < 2; ks++)
            offA[mi][ks] = sw_off(aRow + mi * 16, ks * 2 + ((lane & 16) ? 1 : 0));
#pragma unroll
    for (int n2 = 0; n2 < 4; n2++)
#pragma unroll
        for (int ks = 0; ks < 2; ks++)
            offB[n2][ks] = sw_off(bRow + n2 * 16, ks * 2 + ((lane & 8) ? 1 : 0));

    // staging: row = tid>>1, two 16B chunks per piece
    const __nv_bfloat16* srcs[4] = {Ah, Al, Bh, Bl};
    const int rowbase[4] = {bm, bm, bn, bn};
    const int row = tid >> 1;
    const int ch0 = (tid & 1) * 2;
    int stg_off[2];
    stg_off[0] = sw_off(row, ch0);
    stg_off[1] = sw_off(row, ch0 + 1);

    auto issue_stage = [&](int kt, int sidx) {
        char* st = smem + sidx * STAGE_SW;
        const int k0 = kt << 5;
#pragma unroll
        for (int p = 0; p < 4; p++) {
            const __nv_bfloat16* src = srcs[p] + (size_t)(rowbase[p] + row) * K + k0;
#pragma unroll
            for (int c = 0; c < 2; c++)
                cp_async16(st + p * TILE_SW + stg_off[c], src + (ch0 + c) * 8);
        }
    };

    const int NK = K >> 5;
    issue_stage(0, 0);
    CP_COMMIT();
    issue_stage(1, 1);
    CP_COMMIT();

    int s3 = 0;                         // kt % 3
    for (int kt = 0; kt < NK; kt++) {
        if (kt == NK - 1) { CP_WAIT0(); } else { CP_WAIT1(); }
        __syncthreads();
        if (kt + 2 < NK) {
            int si = s3 + 2; if (si >= 3) si -= 3;
            issue_stage(kt + 2, si);
            CP_COMMIT();
        }

        const char* st = smem + s3 * STAGE_SW;
#pragma unroll
        for (int ks = 0; ks < 2; ks++) {
            uint32_t ah[2][4], al[2][4];
#pragma unroll
            for (int mi = 0; mi < 2; mi++) {
                ldsm_x4p(ah[mi], st + offA[mi][ks]);
                ldsm_x4p(al[mi], st + TILE_SW + offA[mi][ks]);
            }
#pragma unroll
            for (int n2 = 0; n2 < 4; n2++) {
                uint32_t bh[4], bl[4];
                ldsm_x4p(bh, st + 2 * TILE_SW + offB[n2][ks]);
                ldsm_x4p(bl, st + 3 * TILE_SW + offB[n2][ks]);
#pragma unroll
                for (int mi = 0; mi < 2; mi++) {
                    mma16816(acc[mi][2*n2],   ah[mi], bh[0], bh[1]);
                    mma16816(acc[mi][2*n2+1], ah[mi], bh[2], bh[3]);
                    mma16816(acc[mi][2*n2],   ah[mi], bl[0], bl[1]);
                    mma16816(acc[mi][2*n2+1], ah[mi], bl[2], bl[3]);
                    mma16816(acc[mi][2*n2],   al[mi], bh[0], bh[1]);
                    mma16816(acc[mi][2*n2+1], al[mi], bh[2], bh[3]);
                }
            }
        }
        if (++s3 == 3) s3 = 0;
    }

    const int colbase = bn + warpN * 64;

    // fused softmax over 64-col heads (k region of merged qkv projection)
    if (colbase >= sm_lo && colbase < sm_hi) {
#pragma unroll
        for (int mi = 0; mi < 2; mi++) {
#pragma unroll
            for (int hf = 0; hf < 2; hf++) {
                float mx = -3.4e38f;
#pragma unroll
                for (int ni = 0; ni < 8; ni++)
                    mx = fmaxf(mx, fmaxf(acc[mi][ni][2*hf], acc[mi][ni][2*hf+1]));
                mx = fmaxf(mx, __shfl_xor_sync(0xffffffffu, mx, 1));
                mx = fmaxf(mx, __shfl_xor_sync(0xffffffffu, mx, 2));
                float s = 0.f;
#pragma unroll
                for (int ni = 0; ni < 8; ni++) {
                    float e0 = expf(acc[mi][ni][2*hf]     - mx);
                    float e1 = expf(acc[mi][ni][2*hf + 1] - mx);
                    acc[mi][ni][2*hf] = e0; acc[mi][ni][2*hf+1] = e1;
                    s += e0 + e1;
                }
                s += __shfl_xor_sync(0xffffffffu, s, 1);
                s += __shfl_xor_sync(0xffffffffu, s, 2);
                float inv = 1.f / s;
#pragma unroll
                for (int ni = 0; ni < 8; ni++) {
                    acc[mi][ni][2*hf]     *= inv;
                    acc[mi][ni][2*hf + 1] *= inv;
                }
            }
        }
    }

    // epilogue: route by column block (uniform per warp)
    float* Cp; int cb; int ldc;
    if (colbase < csplit) { Cp = C1; cb = colbase; ldc = ld1; }
    else                  { Cp = C2; cb = colbase - csplit; ldc = ld2; }

    const int g = lane >> 2, t = lane & 3;
#pragma unroll
    for (int mi = 0; mi < 2; mi++) {
        int r = bm + warpM * 32 + mi * 16 + g;
#pragma unroll
        for (int ni = 0; ni < 8; ni++) {
            int co = cb + ni * 8 + t * 2;
            float b0 = 0.f, b1 = 0.f;
            if (bias) { b0 = bias[co]; b1 = bias[co + 1]; }
            float2 v0 = {acc[mi][ni][0] + b0, acc[mi][ni][1] + b1};
            float2 v1 = {acc[mi][ni][2] + b0, acc[mi][ni][3] + b1};
            *(float2*)(Cp + (size_t)r * ldc + co)       = v0;
            *(float2*)(Cp + (size_t)(r + 8) * ldc + co) = v1;
        }
    }
}

// ---------------------------------------------------------------------------
// split x (fp32 -> bf16 hi/lo)
// ---------------------------------------------------------------------------
__global__ __launch_bounds__(256) void split_x_kernel(const float* __restrict__ x)
{
    int i = blockIdx.x * 256 + threadIdx.x;
    float4 v = ((const float4*)x)[i];
    float f[4] = {v.x, v.y, v.z, v.w};
    __nv_bfloat162 h01, h23, l01, l23;
    __nv_bfloat16 h, l;
    h = __float2bfloat16_rn(f[0]); l = __float2bfloat16_rn(f[0] - __bfloat162float(h)); h01.x = h; l01.x = l;
    h = __float2bfloat16_rn(f[1]); l = __float2bfloat16_rn(f[1] - __bfloat162float(h)); h01.y = h; l01.y = l;
    h = __float2bfloat16_rn(f[2]); l = __float2bfloat16_rn(f[2] - __bfloat162float(h)); h23.x = h; l23.x = l;
    h = __float2bfloat16_rn(f[3]); l = __float2bfloat16_rn(f[3] - __bfloat162float(h)); h23.y = h; l23.y = l;
    ((__nv_bfloat162*)g_xh)[2 * i] = h01; ((__nv_bfloat162*)g_xh)[2 * i + 1] = h23;
    ((__nv_bfloat162*)g_xl)[2 * i] = l01; ((__nv_bfloat162*)g_xl)[2 * i + 1] = l23;
}

// ---------------------------------------------------------------------------
// all-weights transpose + split (z selects which weight)
// ---------------------------------------------------------------------------
__global__ __launch_bounds__(256) void wsplit_all_kernel(
    const float* __restrict__ wq, const float* __restrict__ wkv,
    const float* __restrict__ wp)
{
    __shared__ float t[32][33];
    const int z = blockIdx.z;
    const float* W; __nv_bfloat16 *Th, *Tl; int K, N, roff;
    if (z == 0)      { W = wq;  K = DIMV; N = DIMV; Th = g_wqkvh; Tl = g_wqkvl; roff = 0;   }
    else if (z == 1) { W = wkv; K = DIMV; N = EDIM; Th = g_wqkvh; Tl = g_wqkvl; roff = DIMV;}
    else             { W = wp;  K = EDIM; N = DIMV; Th = g_wph;   Tl = g_wpl;   roff = 0;   }

    int n0 = blockIdx.x * 32, k0 = blockIdx.y * 32;
    if (n0 >= N || k0 >= K) return;
    int tx = threadIdx.x & 31, ty = threadIdx.x >> 5;
#pragma unroll
    for (int i = 0; i < 4; i++)
        t[ty + i * 8][tx] = W[(size_t)(k0 + ty + i * 8) * N + n0 + tx];
    __syncthreads();
#pragma unroll
    for (int i = 0; i < 4; i++) {
        float f = t[tx][ty + i * 8];
        __nv_bfloat16 h = __float2bfloat16_rn(f);
        __nv_bfloat16 l = __float2bfloat16_rn(f - __bfloat162float(h));
        Th[(size_t)(roff + n0 + ty + i * 8) * K + k0 + tx] = h;
        Tl[(size_t)(roff + n0 + ty + i * 8) * K + k0 + tx] = l;
    }
}

// ---------------------------------------------------------------------------
// ktv partials: block (bh, s of 8); 256 threads = 4 subgroups x 64 threads.
// Subgroup g covers rows [s*512 + g*128, +128) with 8x8 per-thread tiles.
// Chunk index (s*4+g) reproduces the old 128-row chunk order bit-exactly.
// ---------------------------------------------------------------------------
#define KTV_DSMEM (4 * 32 * 64 * 2 * 4)   // 65536 B

__global__ __launch_bounds__(256, 2) void ktv_part_kernel()
{
    extern __shared__ float ksm[];
    int bh = blockIdx.x, s = blockIdx.y;
    int b = bh / HEADS, h = bh % HEADS;
    int tid = threadIdx.x;
    int g = tid >> 6, t = tid & 63;
    int td = t & 7, te = t >> 3;

    float* Kg = ksm + g * (32 * 64);
    float* Vg = ksm + 4 * (32 * 64) + g * (32 * 64);
    const float* base = g_kv + (size_t)b * NN * EDIM + h * HD
                        + (size_t)(s * 512 + g * 128) * EDIM;

    float acc[8][8];
#pragma unroll
    for (int i = 0; i < 8; i++)
#pragma unroll
        for (int j = 0; j < 8; j++) acc[i][j] = 0.f;

    for (int n0 = 0; n0 < 128; n0 += 32) {
#pragma unroll
        for (int i = 0; i < 8; i++) {
            int idx = t + i * 64;                 // 0..511
            int nl = idx >> 4, d4 = (idx & 15) * 4;
            const float* rp = base + (size_t)(n0 + nl) * EDIM;
            *(float4*)&Kg[nl * 64 + d4] = *(const float4*)(rp + d4);
            *(float4*)&Vg[nl * 64 + d4] = *(const float4*)(rp + DIMV + d4);
        }
        __syncthreads();
#pragma unroll 4
        for (int n = 0; n < 32; n++) {
            float a[8], bb[8];
            *(float4*)&a[0]  = *(const float4*)&Kg[n * 64 + td * 8];
            *(float4*)&a[4]  = *(const float4*)&Kg[n * 64 + td * 8 + 4];
            *(float4*)&bb[0] = *(const float4*)&Vg[n * 64 + te * 8];
            *(float4*)&bb[4] = *(const float4*)&Vg[n * 64 + te * 8 + 4];
#pragma unroll
            for (int i = 0; i < 8; i++)
#pragma unroll
                for (int j = 0; j < 8; j++)
                    acc[i][j] += a[i] * bb[j];
        }
        __syncthreads();
    }

    float* out = g_ktvp + ((size_t)(s * 4 + g) * 96 + bh) * HD * HD;
#pragma unroll
    for (int i = 0; i < 8; i++) {
        float4 v0, v1;
        v0.x = acc[i][0]; v0.y = acc[i][1]; v0.z = acc[i][2]; v0.w = acc[i][3];
        v1.x = acc[i][4]; v1.y = acc[i][5]; v1.z = acc[i][6]; v1.w = acc[i][7];
        *(float4*)&out[(td * 8 + i) * 64 + te * 8]     = v0;
        *(float4*)&out[(td * 8 + i) * 64 + te * 8 + 4] = v1;
    }
}

// reduce partials and scatter into both ektv positions (direct + rolled)
__global__ void ktv_reduce_kernel()
{
    int idx = blockIdx.x * 256 + threadIdx.x;
    float s = 0.f;
#pragma unroll
    for (int i = 0; i < KTV_SPLIT; i++)
        s += g_ktvp[(size_t)i * 96 * HD * HD + idx];

    int e = idx & 63;
    int d = (idx >> 6) & 63;
    int bh = idx >> 12;
    int h = bh % HEADS, b = bh / HEADS;
    g_ektv[(((size_t)(b * 24 + h) * 64) + d) * 64 + e] = s;
    int ct = h * 64 + e - 32;
    if (ct < 0) ct += 768;
    int j2 = 12 + (ct >> 6), e2 = ct & 63;
    g_ektv[(((size_t)(b * 24 + j2) * 64) + d) * 64 + e2] = s;
}

// ---------------------------------------------------------------------------
// Fused attn + LePE, rolling 3-slab ring over YG consecutive image rows.
// ---------------------------------------------------------------------------
#define YG 8
#define QS_STRIDE 72
#define AL_ES   0
#define AL_QS   16384
#define AL_WT   (AL_QS + 3*64*QS_STRIDE*4)
#define AL_BS   (AL_WT + 64*9*4)
#define AL_SMEM (AL_BS + 256)

__global__ __launch_bounds__(256) void attn_lepe_kernel(
    const float* __restrict__ w_lepe, const float* __restrict__ b_lepe)
{
    extern __shared__ char sm[];
    float* Es = (float*)(sm + AL_ES);        // [64][64]
    float* Qs = (float*)(sm + AL_QS);        // [3][64][QS_STRIDE] ring
    float* Wt = (float*)(sm + AL_WT);        // [64][9]
    float* Bs = (float*)(sm + AL_BS);        // [64]

    const int Y = blockIdx.x * YG, j = blockIdx.y, b = blockIdx.z;
    const int tid = threadIdx.x;

    const float* ep = g_ektv + (size_t)((b * 24 + j) * 64) * 64;
#pragma unroll
    for (int i = 0; i < 4; i++) {
        int idx4 = tid + i * 256;
        *(float4*)&Es[idx4 * 4] = *(const float4*)(ep + idx4 * 4);
    }
    for (int idx = tid; idx < 64 * 9; idx += 256) Wt[idx] = w_lepe[(j * 64) * 9 + idx];
    if (tid < 64) Bs[tid] = b_lepe[j * 64 + tid];

    const int qbase = (j < 12) ? j * 64 : ((j - 12) * 64 + 32);

    auto load_slab = [&](int y) {
        float* dst = Qs + ((y + 1) % 3) * 64 * QS_STRIDE;
        bool valid = (y >= 0) && (y < 64);
        const float* qrow = g_q + ((size_t)(b * NN) + y * 64) * DIMV;
#pragma unroll
        for (int i = 0; i < 4; i++) {
            int idx4 = tid + i * 256;
            int x = idx4 >> 4, d4 = (idx4 & 15) * 4;
            float4 v = make_float4(0.f, 0.f, 0.f, 0.f);
            if (valid) {
                int c = qbase + d4;
                if (c >= 768) c -= 768;
                v = *(const float4*)(qrow + (size_t)x * DIMV + c);
            }
            *(float4*)&dst[x * QS_STRIDE + d4] = v;
        }
    };

    load_slab(Y - 1);
    load_slab(Y);

    const int r0 = (tid >> 4) * 4, e0 = (tid & 15) * 4;

    for (int yi = 0; yi < YG; yi++) {
        const int y0 = Y + yi;
        load_slab(y0 + 1);
        __syncthreads();

        const float* Qc = Qs + ((y0 + 1) % 3) * 64 * QS_STRIDE;
        float acc[4][4];
#pragma unroll
        for (int i = 0; i < 4; i++)
#pragma unroll
            for (int jj = 0; jj < 4; jj++) acc[i][jj] = 0.f;

#pragma unroll 8
        for (int d = 0; d < 64; d++) {
            float a0[4], b0[4];
            a0[0] = Qc[(r0 + 0) * QS_STRIDE + d];
            a0[1] = Qc[(r0 + 1) * QS_STRIDE + d];
            a0[2] = Qc[(r0 + 2) * QS_STRIDE + d];
            a0[3] = Qc[(r0 + 3) * QS_STRIDE + d];
            *(float4*)b0 = *(const float4*)&Es[d * 64 + e0];
#pragma unroll
            for (int i = 0; i < 4; i++)
#pragma unroll
                for (int jj = 0; jj < 4; jj++)
                    acc[i][jj] += a0[i] * b0[jj];
        }

        const float* slab0 = Qs + ((y0 + 0) % 3) * 64 * QS_STRIDE;
        const float* slab1 = Qc;
        const float* slab2 = Qs + ((y0 + 2) % 3) * 64 * QS_STRIDE;
        const float* slabs[3] = {slab0, slab1, slab2};

        const int n0 = y0 * 64;
#pragma unroll
        for (int i = 0; i < 4; i++) {
            const int x = r0 + i;
            uint32_t hp[2], lp[2];
#pragma unroll
            for (int jj = 0; jj < 4; jj++) {
                const int e = e0 + jj;
                float sum = Bs[e];
#pragma unroll
                for (int ky = 0; ky < 3; ky++) {
#pragma unroll
                    for (int kx = 0; kx < 3; kx++) {
                        int xx = x + kx - 1;
                        float qv = (xx >= 0 && xx < 64) ? slabs[ky][xx * QS_STRIDE + e] : 0.f;
                        sum += Wt[e * 9 + ky * 3 + kx] * qv;
                    }
                }
                float val = 0.125f * acc[i][jj] + sum;
                __nv_bfloat16 h = __float2bfloat16_rn(val);
                __nv_bfloat16 l = __float2bfloat16_rn(val - __bfloat162float(h));
                ((__nv_bfloat16*)hp)[jj] = h;
                ((__nv_bfloat16*)lp)[jj] = l;
            }
            size_t off = ((size_t)(b * NN) + n0 + x) * EDIM + j * 64 + e0;
            *(uint2*)(g_yh + off) = make_uint2(hp[0], hp[1]);
            *(uint2*)(g_yl + off) = make_uint2(lp[0], lp[1]);
        }
        __syncthreads();
    }
}

// ---------------------------------------------------------------------------
extern "C" void kernel_launch(void* const* d_in, const int* in_sizes, int n_in,
                              void* d_out, int out_size)
{
    const float* x      = (const float*)d_in[0];
    const float* w_q    = (const float*)d_in[1];
    const float* w_kv   = (const float*)d_in[2];
    const float* w_proj = (const float*)d_in[3];
    const float* b_proj = (const float*)d_in[4];
    const float* w_lepe = (const float*)d_in[5];
    const float* b_lepe = (const float*)d_in[6];
    float* out = (float*)d_out;

    float* q = nullptr; float* kv = nullptr;
    cudaGetSymbolAddress((void**)&q,  g_q);
    cudaGetSymbolAddress((void**)&kv, g_kv);
    __nv_bfloat16 *xh, *xl, *yh, *yl, *wh, *wl, *wph, *wpl;
    cudaGetSymbolAddress((void**)&xh, g_xh);   cudaGetSymbolAddress((void**)&xl, g_xl);
    cudaGetSymbolAddress((void**)&yh, g_yh);   cudaGetSymbolAddress((void**)&yl, g_yl);
    cudaGetSymbolAddress((void**)&wh, g_wqkvh); cudaGetSymbolAddress((void**)&wl, g_wqkvl);
    cudaGetSymbolAddress((void**)&wph, g_wph); cudaGetSymbolAddress((void**)&wpl, g_wpl);

    static bool attr_set = false;
    if (!attr_set) {
        cudaFuncSetAttribute(gemm_mma, cudaFuncAttributeMaxDynamicSharedMemorySize, GEMM_DSMEM);
        cudaFuncSetAttribute(attn_lepe_kernel, cudaFuncAttributeMaxDynamicSharedMemorySize, AL_SMEM);
        cudaFuncSetAttribute(ktv_part_kernel, cudaFuncAttributeMaxDynamicSharedMemorySize, KTV_DSMEM);
        attr_set = true;
    }

    // 0-1: operand splits
    split_x_kernel<<<(MTOT * DIMV / 4) / 256, 256>>>(x);
    wsplit_all_kernel<<<dim3(48, 48, 3), 256>>>(w_q, w_kv, w_proj);

    // 2: merged q|kv projection with fused k-softmax on cols [768,1536)
    gemm_mma<<<dim3(NQKV / 128, MTOT / 128), 256, GEMM_DSMEM>>>(
        xh, xl, wh, wl, q, kv, DIMV, DIMV, EDIM,
        MTOT, NQKV, DIMV, nullptr, DIMV, 2 * DIMV);

    // 3-4: K^T V split + reduce (scatters into ektv)
    ktv_part_kernel<<<dim3(BB * HEADS, 8), 256, KTV_DSMEM>>>();
    ktv_reduce_kernel<<<(BB * HEADS * HD * HD) / 256, 256>>>();

    // 5: fused attn + LePE (rolling slabs) -> yh/yl
    attn_lepe_kernel<<<dim3(64 / YG, 24, BB), 256, AL_SMEM>>>(w_lepe, b_lepe);

    // 6: output projection + bias
    gemm_mma<<<dim3(DIMV / 128, MTOT / 128), 256, GEMM_DSMEM>>>(
        yh, yl, wph, wpl, out, out, DIMV, DIMV, DIMV,
        MTOT, DIMV, EDIM, b_proj, 0, 0);
}